// round 14
// baseline (speedup 1.0000x reference)
#include <cuda_runtime.h>
#include <cuda_bf16.h>
#include <math.h>
#include <stdint.h>

constexpr int kB   = 4;
constexpr int kTQ  = 2048;
constexpr int kTKV = 2048;
constexpr int kC   = 1024;
constexpr int kD   = 64;
constexpr int kH   = 16;
constexpr int kM   = kB * kTQ;

// RoPE tables
__device__ float g_sin[kTKV * (kD / 2)];
__device__ float g_cos[kTKV * (kD / 2)];
// fp8-gemm A-side: hi bf16 [M,K] + fp8 combo [M,2K] = [x/32 | 32*xlo]
__device__ __nv_bfloat16 g_xqh[(size_t)kM * kC];
__device__ uint8_t       g_xq2[(size_t)kM * 2 * kC];
__device__ __nv_bfloat16 g_xkvh[(size_t)kM * kC];
__device__ uint8_t       g_xkv2[(size_t)kM * 2 * kC];
// fp8-gemm B-side (W*32, transposed): hi bf16 [N,K] + fp8 combo [N,2K] = [32*w'lo | w'/32]
__device__ __nv_bfloat16 g_wqTh[1024 * 1024];
__device__ uint8_t       g_wq2[1024 * 2048];
__device__ __nv_bfloat16 g_wkvTh[2048 * 1024];
__device__ uint8_t       g_wkv2[(size_t)2048 * 2048];
// out-projection weights: bf16x3 path, unscaled
__device__ __nv_bfloat16 g_wcTh[1024 * 1024], g_wcTl[1024 * 1024];
// projected, rope'd, split activations (bf16 hi/lo)
__device__ __nv_bfloat16 g_qh[(size_t)kM * kC], g_ql[(size_t)kM * kC];
__device__ __nv_bfloat16 g_kh[(size_t)kM * kC], g_kl[(size_t)kM * kC];
__device__ __nv_bfloat16 g_vh[(size_t)kM * kC], g_vl[(size_t)kM * kC];
// attention output, bf16 hi/lo
__device__ __nv_bfloat16 g_ah[(size_t)kM * kC], g_al[(size_t)kM * kC];

// ---------------------------------------------------------------------------
__device__ __forceinline__ uint32_t smem_u32(const void* p) {
    return (uint32_t)__cvta_generic_to_shared(p);
}
__device__ __forceinline__ void ldsm_x4(uint32_t* r, uint32_t addr) {
    asm volatile("ldmatrix.sync.aligned.m8n8.x4.shared.b16 {%0,%1,%2,%3}, [%4];"
                 : "=r"(r[0]), "=r"(r[1]), "=r"(r[2]), "=r"(r[3]) : "r"(addr));
}
__device__ __forceinline__ void ldsm_x2(uint32_t* r, uint32_t addr) {
    asm volatile("ldmatrix.sync.aligned.m8n8.x2.shared.b16 {%0,%1}, [%2];"
                 : "=r"(r[0]), "=r"(r[1]) : "r"(addr));
}
__device__ __forceinline__ void ldsm_x4_trans(uint32_t* r, uint32_t addr) {
    asm volatile("ldmatrix.sync.aligned.m8n8.x4.trans.shared.b16 {%0,%1,%2,%3}, [%4];"
                 : "=r"(r[0]), "=r"(r[1]), "=r"(r[2]), "=r"(r[3]) : "r"(addr));
}
__device__ __forceinline__ void mma16816(float* c, const uint32_t* a, const uint32_t* b) {
    asm volatile(
        "mma.sync.aligned.m16n8k16.row.col.f32.bf16.bf16.f32 "
        "{%0,%1,%2,%3}, {%4,%5,%6,%7}, {%8,%9}, {%0,%1,%2,%3};\n"
        : "+f"(c[0]), "+f"(c[1]), "+f"(c[2]), "+f"(c[3])
        : "r"(a[0]), "r"(a[1]), "r"(a[2]), "r"(a[3]), "r"(b[0]), "r"(b[1]));
}
__device__ __forceinline__ void mma_fp8(float* c, const uint32_t* a, const uint32_t* b) {
    asm volatile(
        "mma.sync.aligned.m16n8k32.row.col.f32.e4m3.e4m3.f32 "
        "{%0,%1,%2,%3}, {%4,%5,%6,%7}, {%8,%9}, {%0,%1,%2,%3};\n"
        : "+f"(c[0]), "+f"(c[1]), "+f"(c[2]), "+f"(c[3])
        : "r"(a[0]), "r"(a[1]), "r"(a[2]), "r"(a[3]), "r"(b[0]), "r"(b[1]));
}
__device__ __forceinline__ void split_bf16(float x, __nv_bfloat16& h, __nv_bfloat16& l) {
    h = __float2bfloat16(x);
    l = __float2bfloat16(x - __bfloat162float(h));
}
__device__ __forceinline__ uint32_t pack2(__nv_bfloat16 a, __nv_bfloat16 b) {
    __nv_bfloat162 t; t.x = a; t.y = b;
    return *reinterpret_cast<uint32_t*>(&t);
}
__device__ __forceinline__ uint32_t cvt2_bf16(float lo, float hi) {
    uint32_t r;
    asm("cvt.rn.bf16x2.f32 %0, %1, %2;" : "=r"(r) : "f"(hi), "f"(lo));
    return r;
}
// packs {lo -> byte0, hi -> byte1}
__device__ __forceinline__ uint16_t cvt2_e4m3(float lo, float hi) {
    uint16_t r;
    asm("cvt.rn.satfinite.e4m3x2.f32 %0, %1, %2;" : "=h"(r) : "f"(hi), "f"(lo));
    return r;
}

// ---------------------------------------------------------------------------
__global__ void rope_tables_kernel() {
    int idx = blockIdx.x * blockDim.x + threadIdx.x;
    if (idx >= kTKV * (kD / 2)) return;
    int t = idx >> 5;
    int i = idx & 31;
    double freq = pow(10000.0, -((2.0 * i + 1.0) / (double)kD));
    double ang = (double)(t + 1) * freq;
    g_sin[idx] = (float)sin(ang);
    g_cos[idx] = (float)cos(ang);
}

// X fp32 -> H bf16 + fp8 combo [x/32 | 32*xlo]
__global__ void split_x_kernel(const float* __restrict__ X,
                               __nv_bfloat16* __restrict__ H,
                               uint8_t* __restrict__ X2, int K) {
    int idx = blockIdx.x * blockDim.x + threadIdx.x;
    int m = idx / (K / 16);
    int c = idx % (K / 16);
    const float* xp = X + (size_t)m * K + c * 16;
    uint32_t hbuf[8], mbuf[4], rbuf[4];
#pragma unroll
    for (int u = 0; u < 4; ++u) {
        float4 v = *(const float4*)(xp + u * 4);
        __nv_bfloat16 h0, h1, h2, h3, l0, l1, l2, l3;
        split_bf16(v.x, h0, l0); split_bf16(v.y, h1, l1);
        split_bf16(v.z, h2, l2); split_bf16(v.w, h3, l3);
        hbuf[u * 2 + 0] = pack2(h0, h1);
        hbuf[u * 2 + 1] = pack2(h2, h3);
        uint16_t m0 = cvt2_e4m3(v.x * 0.03125f, v.y * 0.03125f);
        uint16_t m1 = cvt2_e4m3(v.z * 0.03125f, v.w * 0.03125f);
        mbuf[u] = (uint32_t)m0 | ((uint32_t)m1 << 16);
        uint16_t r0 = cvt2_e4m3(__bfloat162float(l0) * 32.f, __bfloat162float(l1) * 32.f);
        uint16_t r1 = cvt2_e4m3(__bfloat162float(l2) * 32.f, __bfloat162float(l3) * 32.f);
        rbuf[u] = (uint32_t)r0 | ((uint32_t)r1 << 16);
    }
    uint4* hp = (uint4*)(H + (size_t)m * K + c * 16);
    hp[0] = make_uint4(hbuf[0], hbuf[1], hbuf[2], hbuf[3]);
    hp[1] = make_uint4(hbuf[4], hbuf[5], hbuf[6], hbuf[7]);
    uint8_t* x2 = X2 + (size_t)m * 2 * K + c * 32;
    *(uint4*)x2        = make_uint4(mbuf[0], mbuf[1], mbuf[2], mbuf[3]);
    *(uint4*)(x2 + 16) = make_uint4(rbuf[0], rbuf[1], rbuf[2], rbuf[3]);
}

// W[K,N] -> w' = 32*W transposed: Thi = bf16(w') [N,K]; fp8 [32*w'lo | w'/32]
__global__ void transpose_split_f8_kernel(const float* __restrict__ W,
                                          __nv_bfloat16* __restrict__ Thi,
                                          uint8_t* __restrict__ T2,
                                          int K, int N) {
    __shared__ float t[32][33];
    int n0 = blockIdx.x * 32, k0 = blockIdx.y * 32;
    for (int r = threadIdx.y; r < 32; r += 8)
        t[r][threadIdx.x] = W[(size_t)(k0 + r) * N + n0 + threadIdx.x];
    __syncthreads();
    for (int r = threadIdx.y; r < 32; r += 8) {
        float wp = t[threadIdx.x][r] * 32.f;   // w'
        __nv_bfloat16 h, l;
        split_bf16(wp, h, l);
        int n = n0 + r, k = k0 + threadIdx.x;
        Thi[(size_t)n * K + k] = h;
        size_t b = (size_t)n * 2 * K + (k >> 4) * 32 + (k & 15);
        T2[b]      = (uint8_t)cvt2_e4m3(__bfloat162float(l) * 32.f, 0.f);
        T2[b + 16] = (uint8_t)cvt2_e4m3(wp * 0.03125f, 0.f);
    }
}

// W[K,N] -> bf16 hi/lo [N,K], unscaled (out-projection)
__global__ void transpose_split_bf_kernel(const float* __restrict__ W,
                                          __nv_bfloat16* __restrict__ Thi,
                                          __nv_bfloat16* __restrict__ Tlo,
                                          int K, int N) {
    __shared__ float t[32][33];
    int n0 = blockIdx.x * 32, k0 = blockIdx.y * 32;
    for (int r = threadIdx.y; r < 32; r += 8)
        t[r][threadIdx.x] = W[(size_t)(k0 + r) * N + n0 + threadIdx.x];
    __syncthreads();
    for (int r = threadIdx.y; r < 32; r += 8) {
        float v = t[threadIdx.x][r];
        __nv_bfloat16 h, l;
        split_bf16(v, h, l);
        size_t o = (size_t)(n0 + r) * K + k0 + threadIdx.x;
        Thi[o] = h;
        Tlo[o] = l;
    }
}

// ---------------------------------------------------------------------------
// fp8-cross GEMM for Q/KV projections (acc = 32 * x@W; epilogue * 1/32).
// Per k16: 1 bf16 mma (hi*hi) + 1 fp8 k32 mma (both cross terms).
// MODE 1: rope + scale(0.125*log2e/32) + split -> Qh/Ql.
// MODE 2: cols<1024 rope + 1/32 + split -> Kh/Kl; else 1/32 + split -> Vh/Vl.
// ---------------------------------------------------------------------------
constexpr int kLD = 40;   // bf16 elems per smem row (80B)
constexpr int kF8LD = 80; // fp8 bytes per smem row (16B-aligned rows)

template <int MODE>
__global__ __launch_bounds__(256)
void gemm_f8_kernel(const __nv_bfloat16* __restrict__ Ah,
                    const uint8_t* __restrict__ A2g,
                    const __nv_bfloat16* __restrict__ Bh,
                    const uint8_t* __restrict__ B2g,
                    __nv_bfloat16* __restrict__ O1h, __nv_bfloat16* __restrict__ O1l,
                    __nv_bfloat16* __restrict__ O2h, __nv_bfloat16* __restrict__ O2l,
                    int M, int N, int K) {
    __shared__ __align__(16) __nv_bfloat16 sAh[128 * kLD];
    __shared__ __align__(16) uint8_t       sA2[128 * kF8LD];
    __shared__ __align__(16) __nv_bfloat16 sBh[128 * kLD];
    __shared__ __align__(16) uint8_t       sB2[128 * kF8LD];

    const int tid  = threadIdx.x;
    const int warp = tid >> 5, lane = tid & 31;
    const int wm = warp >> 2, wn = warp & 3;
    const int m0 = blockIdx.y * 128, n0 = blockIdx.x * 128;

    const int row = tid >> 1;
    const int ko  = (tid & 1) * 16;
    const int kb  = (tid & 1) * 32;
    const __nv_bfloat16* aH = Ah + (size_t)(m0 + row) * K + ko;
    const uint8_t*       a2 = A2g + (size_t)(m0 + row) * 2 * K + kb;
    const __nv_bfloat16* bH = Bh + (size_t)(n0 + row) * K + ko;
    const uint8_t*       b2 = B2g + (size_t)(n0 + row) * 2 * K + kb;

    uint4 pAh[2], pA2[2], pBh[2], pB2[2];
#pragma unroll
    for (int u = 0; u < 2; ++u) {
        pAh[u] = *(const uint4*)(aH + u * 8);
        pA2[u] = *(const uint4*)(a2 + u * 16);
        pBh[u] = *(const uint4*)(bH + u * 8);
        pB2[u] = *(const uint4*)(b2 + u * 16);
    }

    float acc[4][4][4];
#pragma unroll
    for (int mt = 0; mt < 4; ++mt)
#pragma unroll
        for (int nt = 0; nt < 4; ++nt)
#pragma unroll
            for (int e = 0; e < 4; ++e) acc[mt][nt][e] = 0.f;

    const uint32_t sAh_b = smem_u32(sAh), sA2_b = smem_u32(sA2);
    const uint32_t sBh_b = smem_u32(sBh), sB2_b = smem_u32(sB2);
    const int g8 = lane & 7, tq = lane >> 3;

    const uint32_t aRowOff  = (uint32_t)((wm * 64 + ((tq & 1) << 3) + g8) * kLD + ((tq >> 1) << 3)) * 2;
    const uint32_t a2RowOff = (uint32_t)(wm * 64 + ((tq & 1) << 3) + g8) * kF8LD + ((tq >> 1) << 4);
    const uint32_t bRowOff  = (uint32_t)((wn * 32 + g8) * kLD + ((tq & 1) << 3)) * 2;
    const uint32_t b2RowOff = (uint32_t)(wn * 32 + (lane & 7)) * kF8LD + (((lane >> 3) & 1) << 4);

    const int nk = K / 32;
    for (int kt = 0; kt < nk; ++kt) {
#pragma unroll
        for (int u = 0; u < 2; ++u) {
            *(uint4*)&sAh[row * kLD + ko + u * 8]    = pAh[u];
            *(uint4*)&sA2[row * kF8LD + kb + u * 16] = pA2[u];
            *(uint4*)&sBh[row * kLD + ko + u * 8]    = pBh[u];
            *(uint4*)&sB2[row * kF8LD + kb + u * 16] = pB2[u];
        }
        __syncthreads();

        if (kt + 1 < nk) {
            int ke = (kt + 1) * 32;
#pragma unroll
            for (int u = 0; u < 2; ++u) {
                pAh[u] = *(const uint4*)(aH + ke + u * 8);
                pA2[u] = *(const uint4*)(a2 + ke * 2 + u * 16);
                pBh[u] = *(const uint4*)(bH + ke + u * 8);
                pB2[u] = *(const uint4*)(b2 + ke * 2 + u * 16);
            }
        }

#pragma unroll
        for (int s = 0; s < 2; ++s) {
            uint32_t bh[4][2], bq[4][2];
#pragma unroll
            for (int nt = 0; nt < 4; ++nt) {
                ldsm_x2(bh[nt], sBh_b + bRowOff + (uint32_t)(nt * 8 * kLD + s * 16) * 2);
                ldsm_x2(bq[nt], sB2_b + b2RowOff + (uint32_t)(nt * 8 * kF8LD + s * 32));
            }
#pragma unroll
            for (int mt = 0; mt < 4; ++mt) {
                uint32_t ah[4], aq[4];
                ldsm_x4(ah, sAh_b + aRowOff + (uint32_t)(mt * 16 * kLD + s * 16) * 2);
                ldsm_x4(aq, sA2_b + a2RowOff + (uint32_t)(mt * 16 * kF8LD + s * 32));
#pragma unroll
                for (int nt = 0; nt < 4; ++nt) {
                    mma16816(acc[mt][nt], ah, bh[nt]);
                    mma_fp8(acc[mt][nt], aq, bq[nt]);
                }
            }
        }
        __syncthreads();
    }

    // epilogue (acc = 32 * true result)
    const int gq = lane >> 2, tg2 = 2 * (lane & 3);
#pragma unroll
    for (int mt = 0; mt < 4; ++mt) {
#pragma unroll
        for (int nt = 0; nt < 4; ++nt) {
            int col = n0 + wn * 32 + nt * 8 + tg2;
#pragma unroll
            for (int half = 0; half < 2; ++half) {
                int r = m0 + wm * 64 + mt * 16 + gq + half * 8;
                float x = acc[mt][nt][half * 2 + 0];
                float y = acc[mt][nt][half * 2 + 1];
                if (MODE == 1) {
                    int t = r & (kTQ - 1);
                    int i = (col & 63) >> 1;
                    float si = g_sin[t * 32 + i], co = g_cos[t * 32 + i];
                    const float sc = 0.005635527503472513f;  // 0.125*log2(e)/32
                    float xq = (x * co - y * si) * sc;
                    float yq = (x * si + y * co) * sc;
                    __nv_bfloat16 h0, h1, l0, l1;
                    split_bf16(xq, h0, l0);
                    split_bf16(yq, h1, l1);
                    size_t o = (size_t)r * kC + col;
                    *(uint32_t*)(O1h + o) = pack2(h0, h1);
                    *(uint32_t*)(O1l + o) = pack2(l0, l1);
                } else {
                    x *= 0.03125f;
                    y *= 0.03125f;
                    if (col < kC) {
                        int t = r & (kTKV - 1);
                        int i = (col & 63) >> 1;
                        float si = g_sin[t * 32 + i], co = g_cos[t * 32 + i];
                        float xk = x * co - y * si;
                        float yk = x * si + y * co;
                        __nv_bfloat16 h0, h1, l0, l1;
                        split_bf16(xk, h0, l0);
                        split_bf16(yk, h1, l1);
                        size_t o = (size_t)r * kC + col;
                        *(uint32_t*)(O1h + o) = pack2(h0, h1);
                        *(uint32_t*)(O1l + o) = pack2(l0, l1);
                    } else {
                        __nv_bfloat16 h0, h1, l0, l1;
                        split_bf16(x, h0, l0);
                        split_bf16(y, h1, l1);
                        size_t o = (size_t)r * kC + (col - kC);
                        *(uint32_t*)(O2h + o) = pack2(h0, h1);
                        *(uint32_t*)(O2l + o) = pack2(l0, l1);
                    }
                }
            }
        }
    }
}

// ---------------------------------------------------------------------------
// Out-projection GEMM: bf16x3 (R9 proven), fp32 output.
// ---------------------------------------------------------------------------
__global__ __launch_bounds__(256)
void gemm_out_kernel(const __nv_bfloat16* __restrict__ Ah,
                     const __nv_bfloat16* __restrict__ Al,
                     const __nv_bfloat16* __restrict__ Bh,
                     const __nv_bfloat16* __restrict__ Bl,
                     float* __restrict__ Cf, int M, int N, int K) {
    __shared__ __align__(16) __nv_bfloat16 sAh[128 * kLD];
    __shared__ __align__(16) __nv_bfloat16 sAl[128 * kLD];
    __shared__ __align__(16) __nv_bfloat16 sBh[128 * kLD];
    __shared__ __align__(16) __nv_bfloat16 sBl[128 * kLD];

    const int tid  = threadIdx.x;
    const int warp = tid >> 5, lane = tid & 31;
    const int wm = warp >> 2, wn = warp & 3;
    const int m0 = blockIdx.y * 128, n0 = blockIdx.x * 128;

    const int row = tid >> 1;
    const int ko  = (tid & 1) * 16;
    const __nv_bfloat16* aH = Ah + (size_t)(m0 + row) * K + ko;
    const __nv_bfloat16* aL = Al + (size_t)(m0 + row) * K + ko;
    const __nv_bfloat16* bH = Bh + (size_t)(n0 + row) * K + ko;
    const __nv_bfloat16* bL = Bl + (size_t)(n0 + row) * K + ko;

    uint4 pAh[2], pAl[2], pBh[2], pBl[2];
#pragma unroll
    for (int u = 0; u < 2; ++u) {
        pAh[u] = *(const uint4*)(aH + u * 8);
        pAl[u] = *(const uint4*)(aL + u * 8);
        pBh[u] = *(const uint4*)(bH + u * 8);
        pBl[u] = *(const uint4*)(bL + u * 8);
    }

    float acc[4][4][4];
#pragma unroll
    for (int mt = 0; mt < 4; ++mt)
#pragma unroll
        for (int nt = 0; nt < 4; ++nt)
#pragma unroll
            for (int e = 0; e < 4; ++e) acc[mt][nt][e] = 0.f;

    const uint32_t sAh_b = smem_u32(sAh), sAl_b = smem_u32(sAl);
    const uint32_t sBh_b = smem_u32(sBh), sBl_b = smem_u32(sBl);
    const int g8 = lane & 7, tq = lane >> 3;

    const int nk = K / 32;
    for (int kt = 0; kt < nk; ++kt) {
#pragma unroll
        for (int u = 0; u < 2; ++u) {
            *(uint4*)&sAh[row * kLD + ko + u * 8] = pAh[u];
            *(uint4*)&sAl[row * kLD + ko + u * 8] = pAl[u];
            *(uint4*)&sBh[row * kLD + ko + u * 8] = pBh[u];
            *(uint4*)&sBl[row * kLD + ko + u * 8] = pBl[u];
        }
        __syncthreads();

        if (kt + 1 < nk) {
            int kc = (kt + 1) * 32;
#pragma unroll
            for (int u = 0; u < 2; ++u) {
                pAh[u] = *(const uint4*)(aH + kc + u * 8);
                pAl[u] = *(const uint4*)(aL + kc + u * 8);
                pBh[u] = *(const uint4*)(bH + kc + u * 8);
                pBl[u] = *(const uint4*)(bL + kc + u * 8);
            }
        }

#pragma unroll
        for (int s = 0; s < 2; ++s) {
            uint32_t bh[4][2], bl[4][2];
#pragma unroll
            for (int nt = 0; nt < 4; ++nt) {
                uint32_t off = (uint32_t)(((wn * 32 + nt * 8 + g8) * kLD + s * 16 + ((tq & 1) << 3)) * 2);
                ldsm_x2(bh[nt], sBh_b + off);
                ldsm_x2(bl[nt], sBl_b + off);
            }
#pragma unroll
            for (int mt = 0; mt < 4; ++mt) {
                uint32_t offA = (uint32_t)(((wm * 64 + mt * 16 + ((tq & 1) << 3) + g8) * kLD
                                            + s * 16 + ((tq >> 1) << 3)) * 2);
                uint32_t ah[4], al[4];
                ldsm_x4(ah, sAh_b + offA);
                ldsm_x4(al, sAl_b + offA);
#pragma unroll
                for (int nt = 0; nt < 4; ++nt) {
                    mma16816(acc[mt][nt], ah, bh[nt]);
                    mma16816(acc[mt][nt], ah, bl[nt]);
                    mma16816(acc[mt][nt], al, bh[nt]);
                }
            }
        }
        __syncthreads();
    }

    const int gq = lane >> 2, tg2 = 2 * (lane & 3);
#pragma unroll
    for (int mt = 0; mt < 4; ++mt) {
#pragma unroll
        for (int nt = 0; nt < 4; ++nt) {
            int col = n0 + wn * 32 + nt * 8 + tg2;
#pragma unroll
            for (int half = 0; half < 2; ++half) {
                int r = m0 + wm * 64 + mt * 16 + gq + half * 8;
                *(float2*)(Cf + (size_t)r * N + col) =
                    make_float2(acc[mt][nt][half * 2 + 0], acc[mt][nt][half * 2 + 1]);
            }
        }
    }
}

// ---------------------------------------------------------------------------
// Flash attention (R9 proven version, verbatim).
// ---------------------------------------------------------------------------
constexpr int kFQ = 128 * 72;
constexpr int kFT = 64 * 72;
constexpr int kFlashSmem = (2 * kFQ + 8 * kFT) * 2 + 2 * 64 * 4;

__global__ __launch_bounds__(256, 2)
void flash_mma_kernel(const __nv_bfloat16* __restrict__ Qh, const __nv_bfloat16* __restrict__ Ql,
                      const __nv_bfloat16* __restrict__ Kh, const __nv_bfloat16* __restrict__ Kl,
                      const __nv_bfloat16* __restrict__ Vh, const __nv_bfloat16* __restrict__ Vl,
                      const int* __restrict__ qmask, const int* __restrict__ kvmask,
                      __nv_bfloat16* __restrict__ Oh, __nv_bfloat16* __restrict__ Ol) {
    extern __shared__ char smc[];
    __nv_bfloat16* Qhi = (__nv_bfloat16*)smc;
    __nv_bfloat16* Qlo = Qhi + kFQ;
    __nv_bfloat16* Khi = Qlo + kFQ;
    __nv_bfloat16* Klo = Khi + 2 * kFT;
    __nv_bfloat16* Vhi = Klo + 2 * kFT;
    __nv_bfloat16* Vlo = Vhi + 2 * kFT;
    float* km = (float*)(Vlo + 2 * kFT);

    const int tid = threadIdx.x;
    const int warp = tid >> 5, lane = tid & 31;
    const int g = lane >> 2, tg = lane & 3;
    const int m0w = warp * 16;
    const int q0 = blockIdx.x * 128;
    const int h  = blockIdx.y;
    const int b  = blockIdx.z;

    {
        int row = tid >> 1, cb = (tid & 1) * 32;
        size_t src = (size_t)(b * kTQ + q0 + row) * kC + h * 64 + cb;
        int dst = row * 72 + cb;
#pragma unroll
        for (int u = 0; u < 4; ++u) {
            *(uint4*)&Qhi[dst + u * 8] = *(const uint4*)(Qh + src + u * 8);
            *(uint4*)&Qlo[dst + u * 8] = *(const uint4*)(Ql + src + u * 8);
        }
    }
    {
        int j = tid >> 2, cb = (tid & 3) * 16;
        size_t src = (size_t)(b * kTKV + j) * kC + h * 64 + cb;
        int dst = j * 72 + cb;
#pragma unroll
        for (int u = 0; u < 2; ++u) {
            *(uint4*)&Khi[dst + u * 8] = *(const uint4*)(Kh + src + u * 8);
            *(uint4*)&Klo[dst + u * 8] = *(const uint4*)(Kl + src + u * 8);
            *(uint4*)&Vhi[dst + u * 8] = *(const uint4*)(Vh + src + u * 8);
            *(uint4*)&Vlo[dst + u * 8] = *(const uint4*)(Vl + src + u * 8);
        }
        if (tid < 64) km[tid] = (kvmask[b * kTKV + tid] != 0) ? 1.f : 0.f;
    }

    const float qok_g  = (qmask[b * kTQ + q0 + m0w + g]     != 0) ? 1.f : 0.f;
    const float qok_g8 = (qmask[b * kTQ + q0 + m0w + g + 8] != 0) ? 1.f : 0.f;

    float o[8][4];
#pragma unroll
    for (int nt = 0; nt < 8; ++nt)
#pragma unroll
        for (int e = 0; e < 4; ++e) o[nt][e] = 0.f;
    float m_g = -INFINITY, m_g8 = -INFINITY, l_g = 0.f, l_g8 = 0.f;

    const uint32_t Qhi_b = smem_u32(Qhi), Qlo_b = smem_u32(Qlo);
    const uint32_t Khi_b = smem_u32(Khi), Klo_b = smem_u32(Klo);
    const uint32_t Vhi_b = smem_u32(Vhi), Vlo_b = smem_u32(Vlo);

    const uint32_t kPairOff = (uint32_t)((((lane >> 4) << 3) + (lane & 7)) * 72
                                         + (((lane >> 3) & 1) << 3)) * 2;
    const uint32_t vPairOff = (uint32_t)(((((lane >> 3) & 1) << 3) + (lane & 7)) * 72
                                         + ((lane >> 4) << 3)) * 2;

    const int nTiles = kTKV / 64;
    for (int kt = 0; kt < nTiles; ++kt) {
        __syncthreads();
        const int buf = kt & 1;
        const uint32_t kOff = (uint32_t)buf * (kFT * 2);

        if (kt + 1 < nTiles) {
            int k0n = (kt + 1) * 64;
            int nb = buf ^ 1;
            int j = tid >> 2, cb = (tid & 3) * 16;
            size_t src = (size_t)(b * kTKV + k0n + j) * kC + h * 64 + cb;
            int dst = nb * kFT + j * 72 + cb;
#pragma unroll
            for (int u = 0; u < 2; ++u) {
                *(uint4*)&Khi[dst + u * 8] = *(const uint4*)(Kh + src + u * 8);
                *(uint4*)&Klo[dst + u * 8] = *(const uint4*)(Kl + src + u * 8);
                *(uint4*)&Vhi[dst + u * 8] = *(const uint4*)(Vh + src + u * 8);
                *(uint4*)&Vlo[dst + u * 8] = *(const uint4*)(Vl + src + u * 8);
            }
            if (tid < 64) km[nb * 64 + tid] = (kvmask[b * kTKV + k0n + tid] != 0) ? 1.f : 0.f;
        }

        float s[8][4];
#pragma unroll
        for (int nt = 0; nt < 8; ++nt)
#pragma unroll
            for (int e = 0; e < 4; ++e) s[nt][e] = 0.f;

#pragma unroll
        for (int ks = 0; ks < 4; ++ks) {
            uint32_t aoff = (uint32_t)(((m0w + (lane & 15)) * 72 + ks * 16 + ((lane >> 4) << 3)) * 2);
            uint32_t ah[4], al[4];
            ldsm_x4(ah, Qhi_b + aoff);
            ldsm_x4(al, Qlo_b + aoff);
#pragma unroll
            for (int pr = 0; pr < 4; ++pr) {
                uint32_t boff = kPairOff + (uint32_t)(pr * 16 * 72 + ks * 16) * 2 + kOff;
                uint32_t bh[4], bl[4];
                ldsm_x4(bh, Khi_b + boff);
                ldsm_x4(bl, Klo_b + boff);
                mma16816(s[2 * pr],     ah, &bh[0]);
                mma16816(s[2 * pr],     ah, &bl[0]);
                mma16816(s[2 * pr],     al, &bh[0]);
                mma16816(s[2 * pr + 1], ah, &bh[2]);
                mma16816(s[2 * pr + 1], ah, &bl[2]);
                mma16816(s[2 * pr + 1], al, &bh[2]);
            }
        }

        float mx_g = -INFINITY, mx_g8 = -INFINITY;
#pragma unroll
        for (int nt = 0; nt < 8; ++nt) {
            float k0v = km[buf * 64 + nt * 8 + 2 * tg];
            float k1v = km[buf * 64 + nt * 8 + 2 * tg + 1];
            s[nt][0] = (qok_g  * k0v != 0.f) ? s[nt][0] : -1e9f;
            s[nt][1] = (qok_g  * k1v != 0.f) ? s[nt][1] : -1e9f;
            s[nt][2] = (qok_g8 * k0v != 0.f) ? s[nt][2] : -1e9f;
            s[nt][3] = (qok_g8 * k1v != 0.f) ? s[nt][3] : -1e9f;
            mx_g  = fmaxf(mx_g,  fmaxf(s[nt][0], s[nt][1]));
            mx_g8 = fmaxf(mx_g8, fmaxf(s[nt][2], s[nt][3]));
        }
#pragma unroll
        for (int off = 1; off <= 2; off <<= 1) {
            mx_g  = fmaxf(mx_g,  __shfl_xor_sync(0xffffffffu, mx_g,  off));
            mx_g8 = fmaxf(mx_g8, __shfl_xor_sync(0xffffffffu, mx_g8, off));
        }
        float mn_g  = fmaxf(m_g,  mx_g);
        float mn_g8 = fmaxf(m_g8, mx_g8);
        float alpha_g  = exp2f(m_g  - mn_g);
        float alpha_g8 = exp2f(m_g8 - mn_g8);
        m_g = mn_g; m_g8 = mn_g8;

        float sum_g = 0.f, sum_g8 = 0.f;
#pragma unroll
        for (int nt = 0; nt < 8; ++nt) {
            s[nt][0] = exp2f(s[nt][0] - mn_g);
            s[nt][1] = exp2f(s[nt][1] - mn_g);
            s[nt][2] = exp2f(s[nt][2] - mn_g8);
            s[nt][3] = exp2f(s[nt][3] - mn_g8);
            sum_g  += s[nt][0] + s[nt][1];
            sum_g8 += s[nt][2] + s[nt][3];
        }
#pragma unroll
        for (int off = 1; off <= 2; off <<= 1) {
            sum_g  += __shfl_xor_sync(0xffffffffu, sum_g,  off);
            sum_g8 += __shfl_xor_sync(0xffffffffu, sum_g8, off);
        }
        l_g  = l_g  * alpha_g  + sum_g;
        l_g8 = l_g8 * alpha_g8 + sum_g8;
#pragma unroll
        for (int nt = 0; nt < 8; ++nt) {
            o[nt][0] *= alpha_g;  o[nt][1] *= alpha_g;
            o[nt][2] *= alpha_g8; o[nt][3] *= alpha_g8;
        }

#pragma unroll
        for (int ks = 0; ks < 4; ++ks) {
            uint32_t ahi[4], alo[4];
            {
                float p0 = s[2 * ks][0], p1 = s[2 * ks][1];
                float p2 = s[2 * ks][2], p3 = s[2 * ks][3];
                float q0f = s[2 * ks + 1][0], q1f = s[2 * ks + 1][1];
                float q2f = s[2 * ks + 1][2], q3f = s[2 * ks + 1][3];
                ahi[0] = cvt2_bf16(p0, p1);
                ahi[1] = cvt2_bf16(p2, p3);
                ahi[2] = cvt2_bf16(q0f, q1f);
                ahi[3] = cvt2_bf16(q2f, q3f);
                __nv_bfloat162 t;
                t = *(__nv_bfloat162*)&ahi[0];
                alo[0] = cvt2_bf16(p0 - __bfloat162float(t.x), p1 - __bfloat162float(t.y));
                t = *(__nv_bfloat162*)&ahi[1];
                alo[1] = cvt2_bf16(p2 - __bfloat162float(t.x), p3 - __bfloat162float(t.y));
                t = *(__nv_bfloat162*)&ahi[2];
                alo[2] = cvt2_bf16(q0f - __bfloat162float(t.x), q1f - __bfloat162float(t.y));
                t = *(__nv_bfloat162*)&ahi[3];
                alo[3] = cvt2_bf16(q2f - __bfloat162float(t.x), q3f - __bfloat162float(t.y));
            }
#pragma unroll
            for (int pr = 0; pr < 4; ++pr) {
                uint32_t voff = vPairOff + (uint32_t)(ks * 16 * 72 + pr * 16) * 2 + kOff;
                uint32_t vh[4], vl[4];
                ldsm_x4_trans(vh, Vhi_b + voff);
                ldsm_x4_trans(vl, Vlo_b + voff);
                mma16816(o[2 * pr],     ahi, &vh[0]);
                mma16816(o[2 * pr],     alo, &vh[0]);
                mma16816(o[2 * pr],     ahi, &vl[0]);
                mma16816(o[2 * pr + 1], ahi, &vh[2]);
                mma16816(o[2 * pr + 1], alo, &vh[2]);
                mma16816(o[2 * pr + 1], ahi, &vl[2]);
            }
        }
    }

    float inv_g  = 1.f / l_g;
    float inv_g8 = 1.f / l_g8;
    const size_t row_g  = (size_t)(b * kTQ + q0 + m0w + g) * kC + h * 64;
    const size_t row_g8 = row_g + 8 * kC;
#pragma unroll
    for (int nt = 0; nt < 8; ++nt) {
        int col = nt * 8 + 2 * tg;
        {
            float x = o[nt][0] * inv_g, y = o[nt][1] * inv_g;
            __nv_bfloat16 h0, h1, l0, l1;
            split_bf16(x, h0, l0);
            split_bf16(y, h1, l1);
            *(uint32_t*)(Oh + row_g + col) = pack2(h0, h1);
            *(uint32_t*)(Ol + row_g + col) = pack2(l0, l1);
        }
        {
            float x = o[nt][2] * inv_g8, y = o[nt][3] * inv_g8;
            __nv_bfloat16 h0, h1, l0, l1;
            split_bf16(x, h0, l0);
            split_bf16(y, h1, l1);
            *(uint32_t*)(Oh + row_g8 + col) = pack2(h0, h1);
            *(uint32_t*)(Ol + row_g8 + col) = pack2(l0, l1);
        }
    }
}

// ---------------------------------------------------------------------------
extern "C" void kernel_launch(void* const* d_in, const int* in_sizes, int n_in,
                              void* d_out, int out_size) {
    const float* x_q  = (const float*)d_in[0];
    const float* x_kv = (const float*)d_in[1];
    const int* q_mask  = (const int*)d_in[2];
    const int* kv_mask = (const int*)d_in[3];
    const float* W_q  = (const float*)d_in[4];
    const float* W_kv = (const float*)d_in[5];
    const float* W_c  = (const float*)d_in[6];
    float* out = (float*)d_out;

    void* p;
    __nv_bfloat16 *xqh, *xkvh, *wqh, *wkvh, *wch, *wcl;
    uint8_t *xq2, *xkv2, *wq2, *wkv2;
    __nv_bfloat16 *qh, *ql, *kh, *kl, *vh, *vl, *ah, *al;
    cudaGetSymbolAddress(&p, g_xqh);  xqh  = (__nv_bfloat16*)p;
    cudaGetSymbolAddress(&p, g_xq2);  xq2  = (uint8_t*)p;
    cudaGetSymbolAddress(&p, g_xkvh); xkvh = (__nv_bfloat16*)p;
    cudaGetSymbolAddress(&p, g_xkv2); xkv2 = (uint8_t*)p;
    cudaGetSymbolAddress(&p, g_wqTh);  wqh  = (__nv_bfloat16*)p;
    cudaGetSymbolAddress(&p, g_wq2);   wq2  = (uint8_t*)p;
    cudaGetSymbolAddress(&p, g_wkvTh); wkvh = (__nv_bfloat16*)p;
    cudaGetSymbolAddress(&p, g_wkv2);  wkv2 = (uint8_t*)p;
    cudaGetSymbolAddress(&p, g_wcTh);  wch  = (__nv_bfloat16*)p;
    cudaGetSymbolAddress(&p, g_wcTl);  wcl  = (__nv_bfloat16*)p;
    cudaGetSymbolAddress(&p, g_qh); qh = (__nv_bfloat16*)p;
    cudaGetSymbolAddress(&p, g_ql); ql = (__nv_bfloat16*)p;
    cudaGetSymbolAddress(&p, g_kh); kh = (__nv_bfloat16*)p;
    cudaGetSymbolAddress(&p, g_kl); kl = (__nv_bfloat16*)p;
    cudaGetSymbolAddress(&p, g_vh); vh = (__nv_bfloat16*)p;
    cudaGetSymbolAddress(&p, g_vl); vl = (__nv_bfloat16*)p;
    cudaGetSymbolAddress(&p, g_ah); ah = (__nv_bfloat16*)p;
    cudaGetSymbolAddress(&p, g_al); al = (__nv_bfloat16*)p;

    rope_tables_kernel<<<(kTKV * 32 + 255) / 256, 256>>>();

    int chunks = kM * (kC / 16);
    split_x_kernel<<<chunks / 256, 256>>>(x_q,  xqh,  xq2,  kC);
    split_x_kernel<<<chunks / 256, 256>>>(x_kv, xkvh, xkv2, kC);
    transpose_split_f8_kernel<<<dim3(1024 / 32, 1024 / 32), dim3(32, 8)>>>(W_q,  wqh,  wq2,  1024, 1024);
    transpose_split_f8_kernel<<<dim3(2048 / 32, 1024 / 32), dim3(32, 8)>>>(W_kv, wkvh, wkv2, 1024, 2048);
    transpose_split_bf_kernel<<<dim3(1024 / 32, 1024 / 32), dim3(32, 8)>>>(W_c, wch, wcl, 1024, 1024);

    // Q projection + rope + scale(log2e/32) + split
    gemm_f8_kernel<1><<<dim3(kC / 128, kM / 128), 256>>>(
        xqh, xq2, wqh, wq2, qh, ql, nullptr, nullptr, kM, kC, kC);
    // KV projection + rope(K) + 1/32 + split
    gemm_f8_kernel<2><<<dim3(2 * kC / 128, kM / 128), 256>>>(
        xkvh, xkv2, wkvh, wkv2, kh, kl, vh, vl, kM, 2 * kC, kC);

    cudaFuncSetAttribute(flash_mma_kernel, cudaFuncAttributeMaxDynamicSharedMemorySize, kFlashSmem);
    flash_mma_kernel<<<dim3(kTQ / 128, kH, kB), 256, kFlashSmem>>>(
        qh, ql, kh, kl, vh, vl, q_mask, kv_mask, ah, al);

    // output projection (bf16x3) -> fp32 out
    gemm_out_kernel<<<dim3(kC / 128, kM / 128), 256>>>(
        ah, al, wch, wcl, out, kM, kC, kC);
}

// round 15
// speedup vs baseline: 1.1347x; 1.1347x over previous
#include <cuda_runtime.h>
#include <cuda_bf16.h>
#include <cuda_fp16.h>
#include <math.h>
#include <stdint.h>

constexpr int kB   = 4;
constexpr int kTQ  = 2048;
constexpr int kTKV = 2048;
constexpr int kC   = 1024;
constexpr int kD   = 64;
constexpr int kH   = 16;
constexpr int kM   = kB * kTQ;

__device__ float g_sin[kTKV * (kD / 2)];
__device__ float g_cos[kTKV * (kD / 2)];
__device__ __nv_bfloat16 g_xqh[(size_t)kM * kC],  g_xql[(size_t)kM * kC];
__device__ __nv_bfloat16 g_xkvh[(size_t)kM * kC], g_xkvl[(size_t)kM * kC];
__device__ __nv_bfloat16 g_wqTh[1024 * 1024],  g_wqTl[1024 * 1024];
__device__ __nv_bfloat16 g_wkvTh[2048 * 1024], g_wkvTl[2048 * 1024];
__device__ __nv_bfloat16 g_wcTh[1024 * 1024],  g_wcTl[1024 * 1024];
// Q/K: bf16 hi/lo. V: fp16 hi/lo (PV path uses fp16 mma).
__device__ __nv_bfloat16 g_qh[(size_t)kM * kC], g_ql[(size_t)kM * kC];
__device__ __nv_bfloat16 g_kh[(size_t)kM * kC], g_kl[(size_t)kM * kC];
__device__ __half        g_vh[(size_t)kM * kC], g_vl[(size_t)kM * kC];
__device__ __nv_bfloat16 g_ah[(size_t)kM * kC], g_al[(size_t)kM * kC];

// ---------------------------------------------------------------------------
__device__ __forceinline__ uint32_t smem_u32(const void* p) {
    return (uint32_t)__cvta_generic_to_shared(p);
}
__device__ __forceinline__ void ldsm_x4(uint32_t* r, uint32_t addr) {
    asm volatile("ldmatrix.sync.aligned.m8n8.x4.shared.b16 {%0,%1,%2,%3}, [%4];"
                 : "=r"(r[0]), "=r"(r[1]), "=r"(r[2]), "=r"(r[3]) : "r"(addr));
}
__device__ __forceinline__ void ldsm_x2(uint32_t* r, uint32_t addr) {
    asm volatile("ldmatrix.sync.aligned.m8n8.x2.shared.b16 {%0,%1}, [%2];"
                 : "=r"(r[0]), "=r"(r[1]) : "r"(addr));
}
__device__ __forceinline__ void ldsm_x4_trans(uint32_t* r, uint32_t addr) {
    asm volatile("ldmatrix.sync.aligned.m8n8.x4.trans.shared.b16 {%0,%1,%2,%3}, [%4];"
                 : "=r"(r[0]), "=r"(r[1]), "=r"(r[2]), "=r"(r[3]) : "r"(addr));
}
__device__ __forceinline__ void mma16816(float* c, const uint32_t* a, const uint32_t* b) {
    asm volatile(
        "mma.sync.aligned.m16n8k16.row.col.f32.bf16.bf16.f32 "
        "{%0,%1,%2,%3}, {%4,%5,%6,%7}, {%8,%9}, {%0,%1,%2,%3};\n"
        : "+f"(c[0]), "+f"(c[1]), "+f"(c[2]), "+f"(c[3])
        : "r"(a[0]), "r"(a[1]), "r"(a[2]), "r"(a[3]), "r"(b[0]), "r"(b[1]));
}
__device__ __forceinline__ void mma_f16(float* c, const uint32_t* a, const uint32_t* b) {
    asm volatile(
        "mma.sync.aligned.m16n8k16.row.col.f32.f16.f16.f32 "
        "{%0,%1,%2,%3}, {%4,%5,%6,%7}, {%8,%9}, {%0,%1,%2,%3};\n"
        : "+f"(c[0]), "+f"(c[1]), "+f"(c[2]), "+f"(c[3])
        : "r"(a[0]), "r"(a[1]), "r"(a[2]), "r"(a[3]), "r"(b[0]), "r"(b[1]));
}
__device__ __forceinline__ void split_bf16(float x, __nv_bfloat16& h, __nv_bfloat16& l) {
    h = __float2bfloat16(x);
    l = __float2bfloat16(x - __bfloat162float(h));
}
__device__ __forceinline__ uint32_t pack2(__nv_bfloat16 a, __nv_bfloat16 b) {
    __nv_bfloat162 t; t.x = a; t.y = b;
    return *reinterpret_cast<uint32_t*>(&t);
}
__device__ __forceinline__ uint32_t pack2h(__half a, __half b) {
    __half2 t; t.x = a; t.y = b;
    return *reinterpret_cast<uint32_t*>(&t);
}
__device__ __forceinline__ uint32_t cvt2_bf16(float lo, float hi) {
    uint32_t r;
    asm("cvt.rn.bf16x2.f32 %0, %1, %2;" : "=r"(r) : "f"(hi), "f"(lo));
    return r;
}
__device__ __forceinline__ uint32_t cvt2_f16(float lo, float hi) {
    uint32_t r;
    asm("cvt.rn.f16x2.f32 %0, %1, %2;" : "=r"(r) : "f"(hi), "f"(lo));
    return r;
}

// ---------------------------------------------------------------------------
__global__ void rope_tables_kernel() {
    int idx = blockIdx.x * blockDim.x + threadIdx.x;
    if (idx >= kTKV * (kD / 2)) return;
    int t = idx >> 5;
    int i = idx & 31;
    double freq = pow(10000.0, -((2.0 * i + 1.0) / (double)kD));
    double ang = (double)(t + 1) * freq;
    g_sin[idx] = (float)sin(ang);
    g_cos[idx] = (float)cos(ang);
}

__global__ void split_x_kernel(const float* __restrict__ X,
                               __nv_bfloat16* __restrict__ H,
                               __nv_bfloat16* __restrict__ L, int total4) {
    int idx = blockIdx.x * blockDim.x + threadIdx.x;
    if (idx >= total4) return;
    float4 v = ((const float4*)X)[idx];
    __nv_bfloat16 h0, h1, h2, h3, l0, l1, l2, l3;
    split_bf16(v.x, h0, l0); split_bf16(v.y, h1, l1);
    split_bf16(v.z, h2, l2); split_bf16(v.w, h3, l3);
    ((uint2*)H)[idx] = make_uint2(pack2(h0, h1), pack2(h2, h3));
    ((uint2*)L)[idx] = make_uint2(pack2(l0, l1), pack2(l2, l3));
}

__global__ void transpose_split_kernel(const float* __restrict__ W,
                                       __nv_bfloat16* __restrict__ Thi,
                                       __nv_bfloat16* __restrict__ Tlo,
                                       int K, int N) {
    __shared__ float t[32][33];
    int n0 = blockIdx.x * 32, k0 = blockIdx.y * 32;
    for (int r = threadIdx.y; r < 32; r += 8)
        t[r][threadIdx.x] = W[(size_t)(k0 + r) * N + n0 + threadIdx.x];
    __syncthreads();
    for (int r = threadIdx.y; r < 32; r += 8) {
        float v = t[threadIdx.x][r];
        __nv_bfloat16 h, l;
        split_bf16(v, h, l);
        size_t o = (size_t)(n0 + r) * K + k0 + threadIdx.x;
        Thi[o] = h;
        Tlo[o] = l;
    }
}

// ---------------------------------------------------------------------------
// Pre-split bf16x3 GEMM (R9-proven). MODE 0: fp32 C. MODE 1: rope+scale+split Q.
// MODE 2: cols<1024 rope+split K (bf16); cols>=1024 split V (fp16 hi/lo).
// ---------------------------------------------------------------------------
constexpr int kLD = 40;

template <int MODE>
__global__ __launch_bounds__(256)
void gemm_ps_kernel(const __nv_bfloat16* __restrict__ Ah,
                    const __nv_bfloat16* __restrict__ Al,
                    const __nv_bfloat16* __restrict__ Bh,
                    const __nv_bfloat16* __restrict__ Bl,
                    float* __restrict__ Cf,
                    __nv_bfloat16* __restrict__ O1h, __nv_bfloat16* __restrict__ O1l,
                    __half* __restrict__ O2h, __half* __restrict__ O2l,
                    int M, int N, int K) {
    __shared__ __align__(16) __nv_bfloat16 sAh[128 * kLD];
    __shared__ __align__(16) __nv_bfloat16 sAl[128 * kLD];
    __shared__ __align__(16) __nv_bfloat16 sBh[128 * kLD];
    __shared__ __align__(16) __nv_bfloat16 sBl[128 * kLD];

    const int tid  = threadIdx.x;
    const int warp = tid >> 5, lane = tid & 31;
    const int wm = warp >> 2, wn = warp & 3;
    const int m0 = blockIdx.y * 128, n0 = blockIdx.x * 128;

    const int row = tid >> 1;
    const int ko  = (tid & 1) * 16;
    const __nv_bfloat16* aH = Ah + (size_t)(m0 + row) * K + ko;
    const __nv_bfloat16* aL = Al + (size_t)(m0 + row) * K + ko;
    const __nv_bfloat16* bH = Bh + (size_t)(n0 + row) * K + ko;
    const __nv_bfloat16* bL = Bl + (size_t)(n0 + row) * K + ko;

    uint4 pAh[2], pAl[2], pBh[2], pBl[2];
#pragma unroll
    for (int u = 0; u < 2; ++u) {
        pAh[u] = *(const uint4*)(aH + u * 8);
        pAl[u] = *(const uint4*)(aL + u * 8);
        pBh[u] = *(const uint4*)(bH + u * 8);
        pBl[u] = *(const uint4*)(bL + u * 8);
    }

    float acc[4][4][4];
#pragma unroll
    for (int mt = 0; mt < 4; ++mt)
#pragma unroll
        for (int nt = 0; nt < 4; ++nt)
#pragma unroll
            for (int e = 0; e < 4; ++e) acc[mt][nt][e] = 0.f;

    const uint32_t sAh_b = smem_u32(sAh), sAl_b = smem_u32(sAl);
    const uint32_t sBh_b = smem_u32(sBh), sBl_b = smem_u32(sBl);
    const int g8 = lane & 7, tq = lane >> 3;

    const int nk = K / 32;
    for (int kt = 0; kt < nk; ++kt) {
#pragma unroll
        for (int u = 0; u < 2; ++u) {
            *(uint4*)&sAh[row * kLD + ko + u * 8] = pAh[u];
            *(uint4*)&sAl[row * kLD + ko + u * 8] = pAl[u];
            *(uint4*)&sBh[row * kLD + ko + u * 8] = pBh[u];
            *(uint4*)&sBl[row * kLD + ko + u * 8] = pBl[u];
        }
        __syncthreads();

        if (kt + 1 < nk) {
            int kc = (kt + 1) * 32;
#pragma unroll
            for (int u = 0; u < 2; ++u) {
                pAh[u] = *(const uint4*)(aH + kc + u * 8);
                pAl[u] = *(const uint4*)(aL + kc + u * 8);
                pBh[u] = *(const uint4*)(bH + kc + u * 8);
                pBl[u] = *(const uint4*)(bL + kc + u * 8);
            }
        }

#pragma unroll
        for (int s = 0; s < 2; ++s) {
            uint32_t bh[4][2], bl[4][2];
#pragma unroll
            for (int nt = 0; nt < 4; ++nt) {
                uint32_t off = (uint32_t)(((wn * 32 + nt * 8 + g8) * kLD + s * 16 + ((tq & 1) << 3)) * 2);
                ldsm_x2(bh[nt], sBh_b + off);
                ldsm_x2(bl[nt], sBl_b + off);
            }
#pragma unroll
            for (int mt = 0; mt < 4; ++mt) {
                uint32_t offA = (uint32_t)(((wm * 64 + mt * 16 + ((tq & 1) << 3) + g8) * kLD
                                            + s * 16 + ((tq >> 1) << 3)) * 2);
                uint32_t ah[4], al[4];
                ldsm_x4(ah, sAh_b + offA);
                ldsm_x4(al, sAl_b + offA);
#pragma unroll
                for (int nt = 0; nt < 4; ++nt) {
                    mma16816(acc[mt][nt], ah, bh[nt]);
                    mma16816(acc[mt][nt], ah, bl[nt]);
                    mma16816(acc[mt][nt], al, bh[nt]);
                }
            }
        }
        __syncthreads();
    }

    const int gq = lane >> 2, tg2 = 2 * (lane & 3);
#pragma unroll
    for (int mt = 0; mt < 4; ++mt) {
#pragma unroll
        for (int nt = 0; nt < 4; ++nt) {
            int col = n0 + wn * 32 + nt * 8 + tg2;
#pragma unroll
            for (int half = 0; half < 2; ++half) {
                int r = m0 + wm * 64 + mt * 16 + gq + half * 8;
                float x = acc[mt][nt][half * 2 + 0];
                float y = acc[mt][nt][half * 2 + 1];
                if (MODE == 0) {
                    *(float2*)(Cf + (size_t)r * N + col) = make_float2(x, y);
                } else if (MODE == 1) {
                    int t = r & (kTQ - 1);
                    int i = (col & 63) >> 1;
                    float si = g_sin[t * 32 + i], co = g_cos[t * 32 + i];
                    const float sc = 0.18033688011112042f;  // 0.125 * log2(e)
                    float xq = (x * co - y * si) * sc;
                    float yq = (x * si + y * co) * sc;
                    __nv_bfloat16 h0, h1, l0, l1;
                    split_bf16(xq, h0, l0);
                    split_bf16(yq, h1, l1);
                    size_t o = (size_t)r * kC + col;
                    *(uint32_t*)(O1h + o) = pack2(h0, h1);
                    *(uint32_t*)(O1l + o) = pack2(l0, l1);
                } else {
                    if (col < kC) {
                        int t = r & (kTKV - 1);
                        int i = (col & 63) >> 1;
                        float si = g_sin[t * 32 + i], co = g_cos[t * 32 + i];
                        float xk = x * co - y * si;
                        float yk = x * si + y * co;
                        __nv_bfloat16 h0, h1, l0, l1;
                        split_bf16(xk, h0, l0);
                        split_bf16(yk, h1, l1);
                        size_t o = (size_t)r * kC + col;
                        *(uint32_t*)(O1h + o) = pack2(h0, h1);
                        *(uint32_t*)(O1l + o) = pack2(l0, l1);
                    } else {
                        // V: fp16 hi/lo split (22-bit combined accuracy)
                        __half h0 = __float2half(x);
                        __half l0 = __float2half(x - __half2float(h0));
                        __half h1 = __float2half(y);
                        __half l1 = __float2half(y - __half2float(h1));
                        size_t o = (size_t)r * kC + (col - kC);
                        *(uint32_t*)(O2h + o) = pack2h(h0, h1);
                        *(uint32_t*)(O2l + o) = pack2h(l0, l1);
                    }
                }
            }
        }
    }
}

// ---------------------------------------------------------------------------
// Flash attention: S-phase bf16x3 (R9 proven), PV-phase fp16 (P single + V hi/lo).
// ---------------------------------------------------------------------------
constexpr int kFQ = 128 * 72;
constexpr int kFT = 64 * 72;
constexpr int kFlashSmem = (2 * kFQ + 8 * kFT) * 2 + 2 * 64 * 4;

__global__ __launch_bounds__(256, 2)
void flash_mma_kernel(const __nv_bfloat16* __restrict__ Qh, const __nv_bfloat16* __restrict__ Ql,
                      const __nv_bfloat16* __restrict__ Kh, const __nv_bfloat16* __restrict__ Kl,
                      const __half* __restrict__ Vh, const __half* __restrict__ Vl,
                      const int* __restrict__ qmask, const int* __restrict__ kvmask,
                      __nv_bfloat16* __restrict__ Oh, __nv_bfloat16* __restrict__ Ol) {
    extern __shared__ char smc[];
    __nv_bfloat16* Qhi = (__nv_bfloat16*)smc;
    __nv_bfloat16* Qlo = Qhi + kFQ;
    __nv_bfloat16* Khi = Qlo + kFQ;
    __nv_bfloat16* Klo = Khi + 2 * kFT;
    __half* Vhi = (__half*)(Klo + 2 * kFT);
    __half* Vlo = Vhi + 2 * kFT;
    float* km = (float*)(Vlo + 2 * kFT);

    const int tid = threadIdx.x;
    const int warp = tid >> 5, lane = tid & 31;
    const int g = lane >> 2, tg = lane & 3;
    const int m0w = warp * 16;
    const int q0 = blockIdx.x * 128;
    const int h  = blockIdx.y;
    const int b  = blockIdx.z;

    {
        int row = tid >> 1, cb = (tid & 1) * 32;
        size_t src = (size_t)(b * kTQ + q0 + row) * kC + h * 64 + cb;
        int dst = row * 72 + cb;
#pragma unroll
        for (int u = 0; u < 4; ++u) {
            *(uint4*)&Qhi[dst + u * 8] = *(const uint4*)(Qh + src + u * 8);
            *(uint4*)&Qlo[dst + u * 8] = *(const uint4*)(Ql + src + u * 8);
        }
    }
    {
        int j = tid >> 2, cb = (tid & 3) * 16;
        size_t src = (size_t)(b * kTKV + j) * kC + h * 64 + cb;
        int dst = j * 72 + cb;
#pragma unroll
        for (int u = 0; u < 2; ++u) {
            *(uint4*)&Khi[dst + u * 8] = *(const uint4*)(Kh + src + u * 8);
            *(uint4*)&Klo[dst + u * 8] = *(const uint4*)(Kl + src + u * 8);
            *(uint4*)&Vhi[dst + u * 8] = *(const uint4*)(Vh + src + u * 8);
            *(uint4*)&Vlo[dst + u * 8] = *(const uint4*)(Vl + src + u * 8);
        }
        if (tid < 64) km[tid] = (kvmask[b * kTKV + tid] != 0) ? 1.f : 0.f;
    }

    const float qok_g  = (qmask[b * kTQ + q0 + m0w + g]     != 0) ? 1.f : 0.f;
    const float qok_g8 = (qmask[b * kTQ + q0 + m0w + g + 8] != 0) ? 1.f : 0.f;

    float o[8][4];
#pragma unroll
    for (int nt = 0; nt < 8; ++nt)
#pragma unroll
        for (int e = 0; e < 4; ++e) o[nt][e] = 0.f;
    float m_g = -INFINITY, m_g8 = -INFINITY, l_g = 0.f, l_g8 = 0.f;

    const uint32_t Qhi_b = smem_u32(Qhi), Qlo_b = smem_u32(Qlo);
    const uint32_t Khi_b = smem_u32(Khi), Klo_b = smem_u32(Klo);
    const uint32_t Vhi_b = smem_u32(Vhi), Vlo_b = smem_u32(Vlo);

    const uint32_t kPairOff = (uint32_t)((((lane >> 4) << 3) + (lane & 7)) * 72
                                         + (((lane >> 3) & 1) << 3)) * 2;
    const uint32_t vPairOff = (uint32_t)(((((lane >> 3) & 1) << 3) + (lane & 7)) * 72
                                         + ((lane >> 4) << 3)) * 2;

    const int nTiles = kTKV / 64;
    for (int kt = 0; kt < nTiles; ++kt) {
        __syncthreads();
        const int buf = kt & 1;
        const uint32_t kOff = (uint32_t)buf * (kFT * 2);

        if (kt + 1 < nTiles) {
            int k0n = (kt + 1) * 64;
            int nb = buf ^ 1;
            int j = tid >> 2, cb = (tid & 3) * 16;
            size_t src = (size_t)(b * kTKV + k0n + j) * kC + h * 64 + cb;
            int dst = nb * kFT + j * 72 + cb;
#pragma unroll
            for (int u = 0; u < 2; ++u) {
                *(uint4*)&Khi[dst + u * 8] = *(const uint4*)(Kh + src + u * 8);
                *(uint4*)&Klo[dst + u * 8] = *(const uint4*)(Kl + src + u * 8);
                *(uint4*)&Vhi[dst + u * 8] = *(const uint4*)(Vh + src + u * 8);
                *(uint4*)&Vlo[dst + u * 8] = *(const uint4*)(Vl + src + u * 8);
            }
            if (tid < 64) km[nb * 64 + tid] = (kvmask[b * kTKV + k0n + tid] != 0) ? 1.f : 0.f;
        }

        // ---- S = Q K^T (bf16x3) ----
        float s[8][4];
#pragma unroll
        for (int nt = 0; nt < 8; ++nt)
#pragma unroll
            for (int e = 0; e < 4; ++e) s[nt][e] = 0.f;

#pragma unroll
        for (int ks = 0; ks < 4; ++ks) {
            uint32_t aoff = (uint32_t)(((m0w + (lane & 15)) * 72 + ks * 16 + ((lane >> 4) << 3)) * 2);
            uint32_t ah[4], al[4];
            ldsm_x4(ah, Qhi_b + aoff);
            ldsm_x4(al, Qlo_b + aoff);
#pragma unroll
            for (int pr = 0; pr < 4; ++pr) {
                uint32_t boff = kPairOff + (uint32_t)(pr * 16 * 72 + ks * 16) * 2 + kOff;
                uint32_t bh[4], bl[4];
                ldsm_x4(bh, Khi_b + boff);
                ldsm_x4(bl, Klo_b + boff);
                mma16816(s[2 * pr],     ah, &bh[0]);
                mma16816(s[2 * pr],     ah, &bl[0]);
                mma16816(s[2 * pr],     al, &bh[0]);
                mma16816(s[2 * pr + 1], ah, &bh[2]);
                mma16816(s[2 * pr + 1], ah, &bl[2]);
                mma16816(s[2 * pr + 1], al, &bh[2]);
            }
        }

        // ---- mask + online softmax (log2 domain) ----
        float mx_g = -INFINITY, mx_g8 = -INFINITY;
#pragma unroll
        for (int nt = 0; nt < 8; ++nt) {
            float k0v = km[buf * 64 + nt * 8 + 2 * tg];
            float k1v = km[buf * 64 + nt * 8 + 2 * tg + 1];
            s[nt][0] = (qok_g  * k0v != 0.f) ? s[nt][0] : -1e9f;
            s[nt][1] = (qok_g  * k1v != 0.f) ? s[nt][1] : -1e9f;
            s[nt][2] = (qok_g8 * k0v != 0.f) ? s[nt][2] : -1e9f;
            s[nt][3] = (qok_g8 * k1v != 0.f) ? s[nt][3] : -1e9f;
            mx_g  = fmaxf(mx_g,  fmaxf(s[nt][0], s[nt][1]));
            mx_g8 = fmaxf(mx_g8, fmaxf(s[nt][2], s[nt][3]));
        }
#pragma unroll
        for (int off = 1; off <= 2; off <<= 1) {
            mx_g  = fmaxf(mx_g,  __shfl_xor_sync(0xffffffffu, mx_g,  off));
            mx_g8 = fmaxf(mx_g8, __shfl_xor_sync(0xffffffffu, mx_g8, off));
        }
        float mn_g  = fmaxf(m_g,  mx_g);
        float mn_g8 = fmaxf(m_g8, mx_g8);
        float alpha_g  = exp2f(m_g  - mn_g);
        float alpha_g8 = exp2f(m_g8 - mn_g8);
        m_g = mn_g; m_g8 = mn_g8;

        float sum_g = 0.f, sum_g8 = 0.f;
#pragma unroll
        for (int nt = 0; nt < 8; ++nt) {
            s[nt][0] = exp2f(s[nt][0] - mn_g);
            s[nt][1] = exp2f(s[nt][1] - mn_g);
            s[nt][2] = exp2f(s[nt][2] - mn_g8);
            s[nt][3] = exp2f(s[nt][3] - mn_g8);
            sum_g  += s[nt][0] + s[nt][1];
            sum_g8 += s[nt][2] + s[nt][3];
        }
#pragma unroll
        for (int off = 1; off <= 2; off <<= 1) {
            sum_g  += __shfl_xor_sync(0xffffffffu, sum_g,  off);
            sum_g8 += __shfl_xor_sync(0xffffffffu, sum_g8, off);
        }
        l_g  = l_g  * alpha_g  + sum_g;
        l_g8 = l_g8 * alpha_g8 + sum_g8;
#pragma unroll
        for (int nt = 0; nt < 8; ++nt) {
            o[nt][0] *= alpha_g;  o[nt][1] *= alpha_g;
            o[nt][2] *= alpha_g8; o[nt][3] *= alpha_g8;
        }

        // ---- O += P V : P fp16 single, V fp16 hi/lo (2 mma per k16) ----
#pragma unroll
        for (int ks = 0; ks < 4; ++ks) {
            uint32_t pf[4];
            pf[0] = cvt2_f16(s[2 * ks][0],     s[2 * ks][1]);
            pf[1] = cvt2_f16(s[2 * ks][2],     s[2 * ks][3]);
            pf[2] = cvt2_f16(s[2 * ks + 1][0], s[2 * ks + 1][1]);
            pf[3] = cvt2_f16(s[2 * ks + 1][2], s[2 * ks + 1][3]);
#pragma unroll
            for (int pr = 0; pr < 4; ++pr) {
                uint32_t voff = vPairOff + (uint32_t)(ks * 16 * 72 + pr * 16) * 2 + kOff;
                uint32_t vh[4], vl[4];
                ldsm_x4_trans(vh, Vhi_b + voff);
                ldsm_x4_trans(vl, Vlo_b + voff);
                mma_f16(o[2 * pr],     pf, &vh[0]);
                mma_f16(o[2 * pr],     pf, &vl[0]);
                mma_f16(o[2 * pr + 1], pf, &vh[2]);
                mma_f16(o[2 * pr + 1], pf, &vl[2]);
            }
        }
    }

    float inv_g  = 1.f / l_g;
    float inv_g8 = 1.f / l_g8;
    const size_t row_g  = (size_t)(b * kTQ + q0 + m0w + g) * kC + h * 64;
    const size_t row_g8 = row_g + 8 * kC;
#pragma unroll
    for (int nt = 0; nt < 8; ++nt) {
        int col = nt * 8 + 2 * tg;
        {
            float x = o[nt][0] * inv_g, y = o[nt][1] * inv_g;
            __nv_bfloat16 h0, h1, l0, l1;
            split_bf16(x, h0, l0);
            split_bf16(y, h1, l1);
            *(uint32_t*)(Oh + row_g + col) = pack2(h0, h1);
            *(uint32_t*)(Ol + row_g + col) = pack2(l0, l1);
        }
        {
            float x = o[nt][2] * inv_g8, y = o[nt][3] * inv_g8;
            __nv_bfloat16 h0, h1, l0, l1;
            split_bf16(x, h0, l0);
            split_bf16(y, h1, l1);
            *(uint32_t*)(Oh + row_g8 + col) = pack2(h0, h1);
            *(uint32_t*)(Ol + row_g8 + col) = pack2(l0, l1);
        }
    }
}

// ---------------------------------------------------------------------------
extern "C" void kernel_launch(void* const* d_in, const int* in_sizes, int n_in,
                              void* d_out, int out_size) {
    const float* x_q  = (const float*)d_in[0];
    const float* x_kv = (const float*)d_in[1];
    const int* q_mask  = (const int*)d_in[2];
    const int* kv_mask = (const int*)d_in[3];
    const float* W_q  = (const float*)d_in[4];
    const float* W_kv = (const float*)d_in[5];
    const float* W_c  = (const float*)d_in[6];
    float* out = (float*)d_out;

    void* p;
    __nv_bfloat16 *xqh, *xql, *xkvh, *xkvl;
    __nv_bfloat16 *wqh, *wql, *wkvh, *wkvl, *wch, *wcl;
    __nv_bfloat16 *qh, *ql, *kh, *kl, *ah, *al;
    __half *vh, *vl;
    cudaGetSymbolAddress(&p, g_xqh);  xqh  = (__nv_bfloat16*)p;
    cudaGetSymbolAddress(&p, g_xql);  xql  = (__nv_bfloat16*)p;
    cudaGetSymbolAddress(&p, g_xkvh); xkvh = (__nv_bfloat16*)p;
    cudaGetSymbolAddress(&p, g_xkvl); xkvl = (__nv_bfloat16*)p;
    cudaGetSymbolAddress(&p, g_wqTh);  wqh  = (__nv_bfloat16*)p;
    cudaGetSymbolAddress(&p, g_wqTl);  wql  = (__nv_bfloat16*)p;
    cudaGetSymbolAddress(&p, g_wkvTh); wkvh = (__nv_bfloat16*)p;
    cudaGetSymbolAddress(&p, g_wkvTl); wkvl = (__nv_bfloat16*)p;
    cudaGetSymbolAddress(&p, g_wcTh);  wch  = (__nv_bfloat16*)p;
    cudaGetSymbolAddress(&p, g_wcTl);  wcl  = (__nv_bfloat16*)p;
    cudaGetSymbolAddress(&p, g_qh); qh = (__nv_bfloat16*)p;
    cudaGetSymbolAddress(&p, g_ql); ql = (__nv_bfloat16*)p;
    cudaGetSymbolAddress(&p, g_kh); kh = (__nv_bfloat16*)p;
    cudaGetSymbolAddress(&p, g_kl); kl = (__nv_bfloat16*)p;
    cudaGetSymbolAddress(&p, g_vh); vh = (__half*)p;
    cudaGetSymbolAddress(&p, g_vl); vl = (__half*)p;
    cudaGetSymbolAddress(&p, g_ah); ah = (__nv_bfloat16*)p;
    cudaGetSymbolAddress(&p, g_al); al = (__nv_bfloat16*)p;

    rope_tables_kernel<<<(kTKV * 32 + 255) / 256, 256>>>();

    int total4 = kM * kC / 4;
    split_x_kernel<<<(total4 + 255) / 256, 256>>>(x_q,  xqh,  xql,  total4);
    split_x_kernel<<<(total4 + 255) / 256, 256>>>(x_kv, xkvh, xkvl, total4);
    transpose_split_kernel<<<dim3(1024 / 32, 1024 / 32), dim3(32, 8)>>>(W_q,  wqh,  wql,  1024, 1024);
    transpose_split_kernel<<<dim3(2048 / 32, 1024 / 32), dim3(32, 8)>>>(W_kv, wkvh, wkvl, 1024, 2048);
    transpose_split_kernel<<<dim3(1024 / 32, 1024 / 32), dim3(32, 8)>>>(W_c,  wch,  wcl,  1024, 1024);

    // Q projection + rope + scale(log2e) + split
    gemm_ps_kernel<1><<<dim3(kC / 128, kM / 128), 256>>>(
        xqh, xql, wqh, wql, nullptr, qh, ql, nullptr, nullptr, kM, kC, kC);
    // KV projection + rope(K) + split (V as fp16 hi/lo)
    gemm_ps_kernel<2><<<dim3(2 * kC / 128, kM / 128), 256>>>(
        xkvh, xkvl, wkvh, wkvl, nullptr, kh, kl, vh, vl, kM, 2 * kC, kC);

    cudaFuncSetAttribute(flash_mma_kernel, cudaFuncAttributeMaxDynamicSharedMemorySize, kFlashSmem);
    flash_mma_kernel<<<dim3(kTQ / 128, kH, kB), 256, kFlashSmem>>>(
        qh, ql, kh, kl, vh, vl, q_mask, kv_mask, ah, al);

    // output projection (bf16x3) -> fp32 out
    gemm_ps_kernel<0><<<dim3(kC / 128, kM / 128), 256>>>(
        ah, al, wch, wcl, out, nullptr, nullptr, nullptr, nullptr, kM, kC, kC);
}

// round 16
// speedup vs baseline: 1.2999x; 1.1455x over previous
#include <cuda_runtime.h>
#include <cuda_bf16.h>
#include <cuda_fp16.h>
#include <math.h>
#include <stdint.h>

constexpr int kB   = 4;
constexpr int kTQ  = 2048;
constexpr int kTKV = 2048;
constexpr int kC   = 1024;
constexpr int kD   = 64;
constexpr int kH   = 16;
constexpr int kM   = kB * kTQ;

__device__ float g_sin[kTKV * (kD / 2)];
__device__ float g_cos[kTKV * (kD / 2)];
__device__ __nv_bfloat16 g_xqh[(size_t)kM * kC],  g_xql[(size_t)kM * kC];
__device__ __nv_bfloat16 g_xkvh[(size_t)kM * kC], g_xkvl[(size_t)kM * kC];
__device__ __nv_bfloat16 g_wqTh[1024 * 1024],  g_wqTl[1024 * 1024];
__device__ __nv_bfloat16 g_wkvTh[2048 * 1024], g_wkvTl[2048 * 1024];
__device__ __nv_bfloat16 g_wcTh[1024 * 1024],  g_wcTl[1024 * 1024];
// Q/K: single fp16. V: fp16 hi/lo.
__device__ __half g_qf[(size_t)kM * kC];
__device__ __half g_kf[(size_t)kM * kC];
__device__ __half g_vh[(size_t)kM * kC], g_vl[(size_t)kM * kC];
__device__ __nv_bfloat16 g_ah[(size_t)kM * kC], g_al[(size_t)kM * kC];

// ---------------------------------------------------------------------------
__device__ __forceinline__ uint32_t smem_u32(const void* p) {
    return (uint32_t)__cvta_generic_to_shared(p);
}
__device__ __forceinline__ void ldsm_x4(uint32_t* r, uint32_t addr) {
    asm volatile("ldmatrix.sync.aligned.m8n8.x4.shared.b16 {%0,%1,%2,%3}, [%4];"
                 : "=r"(r[0]), "=r"(r[1]), "=r"(r[2]), "=r"(r[3]) : "r"(addr));
}
__device__ __forceinline__ void ldsm_x2(uint32_t* r, uint32_t addr) {
    asm volatile("ldmatrix.sync.aligned.m8n8.x2.shared.b16 {%0,%1}, [%2];"
                 : "=r"(r[0]), "=r"(r[1]) : "r"(addr));
}
__device__ __forceinline__ void ldsm_x4_trans(uint32_t* r, uint32_t addr) {
    asm volatile("ldmatrix.sync.aligned.m8n8.x4.trans.shared.b16 {%0,%1,%2,%3}, [%4];"
                 : "=r"(r[0]), "=r"(r[1]), "=r"(r[2]), "=r"(r[3]) : "r"(addr));
}
__device__ __forceinline__ void mma16816(float* c, const uint32_t* a, const uint32_t* b) {
    asm volatile(
        "mma.sync.aligned.m16n8k16.row.col.f32.bf16.bf16.f32 "
        "{%0,%1,%2,%3}, {%4,%5,%6,%7}, {%8,%9}, {%0,%1,%2,%3};\n"
        : "+f"(c[0]), "+f"(c[1]), "+f"(c[2]), "+f"(c[3])
        : "r"(a[0]), "r"(a[1]), "r"(a[2]), "r"(a[3]), "r"(b[0]), "r"(b[1]));
}
__device__ __forceinline__ void mma_f16(float* c, const uint32_t* a, const uint32_t* b) {
    asm volatile(
        "mma.sync.aligned.m16n8k16.row.col.f32.f16.f16.f32 "
        "{%0,%1,%2,%3}, {%4,%5,%6,%7}, {%8,%9}, {%0,%1,%2,%3};\n"
        : "+f"(c[0]), "+f"(c[1]), "+f"(c[2]), "+f"(c[3])
        : "r"(a[0]), "r"(a[1]), "r"(a[2]), "r"(a[3]), "r"(b[0]), "r"(b[1]));
}
__device__ __forceinline__ void split_bf16(float x, __nv_bfloat16& h, __nv_bfloat16& l) {
    h = __float2bfloat16(x);
    l = __float2bfloat16(x - __bfloat162float(h));
}
__device__ __forceinline__ uint32_t pack2(__nv_bfloat16 a, __nv_bfloat16 b) {
    __nv_bfloat162 t; t.x = a; t.y = b;
    return *reinterpret_cast<uint32_t*>(&t);
}
__device__ __forceinline__ uint32_t pack2h(__half a, __half b) {
    __half2 t; t.x = a; t.y = b;
    return *reinterpret_cast<uint32_t*>(&t);
}
__device__ __forceinline__ uint32_t cvt2_f16(float lo, float hi) {
    uint32_t r;
    asm("cvt.rn.f16x2.f32 %0, %1, %2;" : "=r"(r) : "f"(hi), "f"(lo));
    return r;
}

// ---------------------------------------------------------------------------
__global__ void rope_tables_kernel() {
    int idx = blockIdx.x * blockDim.x + threadIdx.x;
    if (idx >= kTKV * (kD / 2)) return;
    int t = idx >> 5;
    int i = idx & 31;
    double freq = pow(10000.0, -((2.0 * i + 1.0) / (double)kD));
    double ang = (double)(t + 1) * freq;
    g_sin[idx] = (float)sin(ang);
    g_cos[idx] = (float)cos(ang);
}

__global__ void split_x_kernel(const float* __restrict__ X,
                               __nv_bfloat16* __restrict__ H,
                               __nv_bfloat16* __restrict__ L, int total4) {
    int idx = blockIdx.x * blockDim.x + threadIdx.x;
    if (idx >= total4) return;
    float4 v = ((const float4*)X)[idx];
    __nv_bfloat16 h0, h1, h2, h3, l0, l1, l2, l3;
    split_bf16(v.x, h0, l0); split_bf16(v.y, h1, l1);
    split_bf16(v.z, h2, l2); split_bf16(v.w, h3, l3);
    ((uint2*)H)[idx] = make_uint2(pack2(h0, h1), pack2(h2, h3));
    ((uint2*)L)[idx] = make_uint2(pack2(l0, l1), pack2(l2, l3));
}

__global__ void transpose_split_kernel(const float* __restrict__ W,
                                       __nv_bfloat16* __restrict__ Thi,
                                       __nv_bfloat16* __restrict__ Tlo,
                                       int K, int N) {
    __shared__ float t[32][33];
    int n0 = blockIdx.x * 32, k0 = blockIdx.y * 32;
    for (int r = threadIdx.y; r < 32; r += 8)
        t[r][threadIdx.x] = W[(size_t)(k0 + r) * N + n0 + threadIdx.x];
    __syncthreads();
    for (int r = threadIdx.y; r < 32; r += 8) {
        float v = t[threadIdx.x][r];
        __nv_bfloat16 h, l;
        split_bf16(v, h, l);
        size_t o = (size_t)(n0 + r) * K + k0 + threadIdx.x;
        Thi[o] = h;
        Tlo[o] = l;
    }
}

// ---------------------------------------------------------------------------
// Pre-split bf16x3 GEMM (R9-proven mainloop).
// MODE 0: fp32 C. MODE 1: rope+scale -> fp16 Q (single).
// MODE 2: cols<1024 rope -> fp16 K (single); cols>=1024 -> fp16 V hi/lo.
// ---------------------------------------------------------------------------
constexpr int kLD = 40;

template <int MODE>
__global__ __launch_bounds__(256)
void gemm_ps_kernel(const __nv_bfloat16* __restrict__ Ah,
                    const __nv_bfloat16* __restrict__ Al,
                    const __nv_bfloat16* __restrict__ Bh,
                    const __nv_bfloat16* __restrict__ Bl,
                    float* __restrict__ Cf,
                    __half* __restrict__ O1f,
                    __half* __restrict__ O2h, __half* __restrict__ O2l,
                    int M, int N, int K) {
    __shared__ __align__(16) __nv_bfloat16 sAh[128 * kLD];
    __shared__ __align__(16) __nv_bfloat16 sAl[128 * kLD];
    __shared__ __align__(16) __nv_bfloat16 sBh[128 * kLD];
    __shared__ __align__(16) __nv_bfloat16 sBl[128 * kLD];

    const int tid  = threadIdx.x;
    const int warp = tid >> 5, lane = tid & 31;
    const int wm = warp >> 2, wn = warp & 3;
    const int m0 = blockIdx.y * 128, n0 = blockIdx.x * 128;

    const int row = tid >> 1;
    const int ko  = (tid & 1) * 16;
    const __nv_bfloat16* aH = Ah + (size_t)(m0 + row) * K + ko;
    const __nv_bfloat16* aL = Al + (size_t)(m0 + row) * K + ko;
    const __nv_bfloat16* bH = Bh + (size_t)(n0 + row) * K + ko;
    const __nv_bfloat16* bL = Bl + (size_t)(n0 + row) * K + ko;

    uint4 pAh[2], pAl[2], pBh[2], pBl[2];
#pragma unroll
    for (int u = 0; u < 2; ++u) {
        pAh[u] = *(const uint4*)(aH + u * 8);
        pAl[u] = *(const uint4*)(aL + u * 8);
        pBh[u] = *(const uint4*)(bH + u * 8);
        pBl[u] = *(const uint4*)(bL + u * 8);
    }

    float acc[4][4][4];
#pragma unroll
    for (int mt = 0; mt < 4; ++mt)
#pragma unroll
        for (int nt = 0; nt < 4; ++nt)
#pragma unroll
            for (int e = 0; e < 4; ++e) acc[mt][nt][e] = 0.f;

    const uint32_t sAh_b = smem_u32(sAh), sAl_b = smem_u32(sAl);
    const uint32_t sBh_b = smem_u32(sBh), sBl_b = smem_u32(sBl);
    const int g8 = lane & 7, tq = lane >> 3;

    const int nk = K / 32;
    for (int kt = 0; kt < nk; ++kt) {
#pragma unroll
        for (int u = 0; u < 2; ++u) {
            *(uint4*)&sAh[row * kLD + ko + u * 8] = pAh[u];
            *(uint4*)&sAl[row * kLD + ko + u * 8] = pAl[u];
            *(uint4*)&sBh[row * kLD + ko + u * 8] = pBh[u];
            *(uint4*)&sBl[row * kLD + ko + u * 8] = pBl[u];
        }
        __syncthreads();

        if (kt + 1 < nk) {
            int kc = (kt + 1) * 32;
#pragma unroll
            for (int u = 0; u < 2; ++u) {
                pAh[u] = *(const uint4*)(aH + kc + u * 8);
                pAl[u] = *(const uint4*)(aL + kc + u * 8);
                pBh[u] = *(const uint4*)(bH + kc + u * 8);
                pBl[u] = *(const uint4*)(bL + kc + u * 8);
            }
        }

#pragma unroll
        for (int s = 0; s < 2; ++s) {
            uint32_t bh[4][2], bl[4][2];
#pragma unroll
            for (int nt = 0; nt < 4; ++nt) {
                uint32_t off = (uint32_t)(((wn * 32 + nt * 8 + g8) * kLD + s * 16 + ((tq & 1) << 3)) * 2);
                ldsm_x2(bh[nt], sBh_b + off);
                ldsm_x2(bl[nt], sBl_b + off);
            }
#pragma unroll
            for (int mt = 0; mt < 4; ++mt) {
                uint32_t offA = (uint32_t)(((wm * 64 + mt * 16 + ((tq & 1) << 3) + g8) * kLD
                                            + s * 16 + ((tq >> 1) << 3)) * 2);
                uint32_t ah[4], al[4];
                ldsm_x4(ah, sAh_b + offA);
                ldsm_x4(al, sAl_b + offA);
#pragma unroll
                for (int nt = 0; nt < 4; ++nt) {
                    mma16816(acc[mt][nt], ah, bh[nt]);
                    mma16816(acc[mt][nt], ah, bl[nt]);
                    mma16816(acc[mt][nt], al, bh[nt]);
                }
            }
        }
        __syncthreads();
    }

    const int gq = lane >> 2, tg2 = 2 * (lane & 3);
#pragma unroll
    for (int mt = 0; mt < 4; ++mt) {
#pragma unroll
        for (int nt = 0; nt < 4; ++nt) {
            int col = n0 + wn * 32 + nt * 8 + tg2;
#pragma unroll
            for (int half = 0; half < 2; ++half) {
                int r = m0 + wm * 64 + mt * 16 + gq + half * 8;
                float x = acc[mt][nt][half * 2 + 0];
                float y = acc[mt][nt][half * 2 + 1];
                if (MODE == 0) {
                    *(float2*)(Cf + (size_t)r * N + col) = make_float2(x, y);
                } else if (MODE == 1) {
                    int t = r & (kTQ - 1);
                    int i = (col & 63) >> 1;
                    float si = g_sin[t * 32 + i], co = g_cos[t * 32 + i];
                    const float sc = 0.18033688011112042f;  // 0.125 * log2(e)
                    float xq = (x * co - y * si) * sc;
                    float yq = (x * si + y * co) * sc;
                    size_t o = (size_t)r * kC + col;
                    *(uint32_t*)(O1f + o) = cvt2_f16(xq, yq);
                } else {
                    if (col < kC) {
                        int t = r & (kTKV - 1);
                        int i = (col & 63) >> 1;
                        float si = g_sin[t * 32 + i], co = g_cos[t * 32 + i];
                        float xk = x * co - y * si;
                        float yk = x * si + y * co;
                        size_t o = (size_t)r * kC + col;
                        *(uint32_t*)(O1f + o) = cvt2_f16(xk, yk);
                    } else {
                        __half h0 = __float2half(x);
                        __half l0 = __float2half(x - __half2float(h0));
                        __half h1 = __float2half(y);
                        __half l1 = __float2half(y - __half2float(h1));
                        size_t o = (size_t)r * kC + (col - kC);
                        *(uint32_t*)(O2h + o) = pack2h(h0, h1);
                        *(uint32_t*)(O2l + o) = pack2h(l0, l1);
                    }
                }
            }
        }
    }
}

// ---------------------------------------------------------------------------
// Flash attention: S-phase fp16 single (1 mma/k16), PV-phase fp16 P + V hi/lo.
// ---------------------------------------------------------------------------
constexpr int kFQ = 128 * 72;   // fp16 elems
constexpr int kFT = 64 * 72;
// Qf + K(2 bufs) + Vhi(2) + Vlo(2), fp16; + km 2*64 floats
constexpr int kFlashSmem = (kFQ + 6 * kFT) * 2 + 2 * 64 * 4;   // 74240 B

__global__ __launch_bounds__(256, 2)
void flash_mma_kernel(const __half* __restrict__ Qf,
                      const __half* __restrict__ Kf,
                      const __half* __restrict__ Vh, const __half* __restrict__ Vl,
                      const int* __restrict__ qmask, const int* __restrict__ kvmask,
                      __nv_bfloat16* __restrict__ Oh, __nv_bfloat16* __restrict__ Ol) {
    extern __shared__ char smc[];
    __half* Qs = (__half*)smc;           // [128][72]
    __half* Ks = Qs + kFQ;               // [2][64*72]
    __half* Vhi = Ks + 2 * kFT;
    __half* Vlo = Vhi + 2 * kFT;
    float* km = (float*)(Vlo + 2 * kFT);

    const int tid = threadIdx.x;
    const int warp = tid >> 5, lane = tid & 31;
    const int g = lane >> 2, tg = lane & 3;
    const int m0w = warp * 16;
    const int q0 = blockIdx.x * 128;
    const int h  = blockIdx.y;
    const int b  = blockIdx.z;

    {
        int row = tid >> 1, cb = (tid & 1) * 32;
        size_t src = (size_t)(b * kTQ + q0 + row) * kC + h * 64 + cb;
        int dst = row * 72 + cb;
#pragma unroll
        for (int u = 0; u < 4; ++u)
            *(uint4*)&Qs[dst + u * 8] = *(const uint4*)(Qf + src + u * 8);
    }
    {
        int j = tid >> 2, cb = (tid & 3) * 16;
        size_t src = (size_t)(b * kTKV + j) * kC + h * 64 + cb;
        int dst = j * 72 + cb;
#pragma unroll
        for (int u = 0; u < 2; ++u) {
            *(uint4*)&Ks[dst + u * 8]  = *(const uint4*)(Kf + src + u * 8);
            *(uint4*)&Vhi[dst + u * 8] = *(const uint4*)(Vh + src + u * 8);
            *(uint4*)&Vlo[dst + u * 8] = *(const uint4*)(Vl + src + u * 8);
        }
        if (tid < 64) km[tid] = (kvmask[b * kTKV + tid] != 0) ? 1.f : 0.f;
    }

    const float qok_g  = (qmask[b * kTQ + q0 + m0w + g]     != 0) ? 1.f : 0.f;
    const float qok_g8 = (qmask[b * kTQ + q0 + m0w + g + 8] != 0) ? 1.f : 0.f;

    float o[8][4];
#pragma unroll
    for (int nt = 0; nt < 8; ++nt)
#pragma unroll
        for (int e = 0; e < 4; ++e) o[nt][e] = 0.f;
    float m_g = -INFINITY, m_g8 = -INFINITY, l_g = 0.f, l_g8 = 0.f;

    const uint32_t Qs_b = smem_u32(Qs);
    const uint32_t Ks_b = smem_u32(Ks);
    const uint32_t Vhi_b = smem_u32(Vhi), Vlo_b = smem_u32(Vlo);

    const uint32_t kPairOff = (uint32_t)((((lane >> 4) << 3) + (lane & 7)) * 72
                                         + (((lane >> 3) & 1) << 3)) * 2;
    const uint32_t vPairOff = (uint32_t)(((((lane >> 3) & 1) << 3) + (lane & 7)) * 72
                                         + ((lane >> 4) << 3)) * 2;

    const int nTiles = kTKV / 64;
    for (int kt = 0; kt < nTiles; ++kt) {
        __syncthreads();
        const int buf = kt & 1;
        const uint32_t kOff = (uint32_t)buf * (kFT * 2);

        if (kt + 1 < nTiles) {
            int k0n = (kt + 1) * 64;
            int nb = buf ^ 1;
            int j = tid >> 2, cb = (tid & 3) * 16;
            size_t src = (size_t)(b * kTKV + k0n + j) * kC + h * 64 + cb;
            int dst = nb * kFT + j * 72 + cb;
#pragma unroll
            for (int u = 0; u < 2; ++u) {
                *(uint4*)&Ks[dst + u * 8]  = *(const uint4*)(Kf + src + u * 8);
                *(uint4*)&Vhi[dst + u * 8] = *(const uint4*)(Vh + src + u * 8);
                *(uint4*)&Vlo[dst + u * 8] = *(const uint4*)(Vl + src + u * 8);
            }
            if (tid < 64) km[nb * 64 + tid] = (kvmask[b * kTKV + k0n + tid] != 0) ? 1.f : 0.f;
        }

        // ---- S = Q K^T (fp16 single: 1 mma per k16 per n8-tile) ----
        float s[8][4];
#pragma unroll
        for (int nt = 0; nt < 8; ++nt)
#pragma unroll
            for (int e = 0; e < 4; ++e) s[nt][e] = 0.f;

#pragma unroll
        for (int ks = 0; ks < 4; ++ks) {
            uint32_t aoff = (uint32_t)(((m0w + (lane & 15)) * 72 + ks * 16 + ((lane >> 4) << 3)) * 2);
            uint32_t aq[4];
            ldsm_x4(aq, Qs_b + aoff);
#pragma unroll
            for (int pr = 0; pr < 4; ++pr) {
                uint32_t boff = kPairOff + (uint32_t)(pr * 16 * 72 + ks * 16) * 2 + kOff;
                uint32_t bk[4];
                ldsm_x4(bk, Ks_b + boff);
                mma_f16(s[2 * pr],     aq, &bk[0]);
                mma_f16(s[2 * pr + 1], aq, &bk[2]);
            }
        }

        // ---- mask + online softmax (log2 domain) ----
        float mx_g = -INFINITY, mx_g8 = -INFINITY;
#pragma unroll
        for (int nt = 0; nt < 8; ++nt) {
            float k0v = km[buf * 64 + nt * 8 + 2 * tg];
            float k1v = km[buf * 64 + nt * 8 + 2 * tg + 1];
            s[nt][0] = (qok_g  * k0v != 0.f) ? s[nt][0] : -1e9f;
            s[nt][1] = (qok_g  * k1v != 0.f) ? s[nt][1] : -1e9f;
            s[nt][2] = (qok_g8 * k0v != 0.f) ? s[nt][2] : -1e9f;
            s[nt][3] = (qok_g8 * k1v != 0.f) ? s[nt][3] : -1e9f;
            mx_g  = fmaxf(mx_g,  fmaxf(s[nt][0], s[nt][1]));
            mx_g8 = fmaxf(mx_g8, fmaxf(s[nt][2], s[nt][3]));
        }
#pragma unroll
        for (int off = 1; off <= 2; off <<= 1) {
            mx_g  = fmaxf(mx_g,  __shfl_xor_sync(0xffffffffu, mx_g,  off));
            mx_g8 = fmaxf(mx_g8, __shfl_xor_sync(0xffffffffu, mx_g8, off));
        }
        float mn_g  = fmaxf(m_g,  mx_g);
        float mn_g8 = fmaxf(m_g8, mx_g8);
        float alpha_g  = exp2f(m_g  - mn_g);
        float alpha_g8 = exp2f(m_g8 - mn_g8);
        m_g = mn_g; m_g8 = mn_g8;

        float sum_g = 0.f, sum_g8 = 0.f;
#pragma unroll
        for (int nt = 0; nt < 8; ++nt) {
            s[nt][0] = exp2f(s[nt][0] - mn_g);
            s[nt][1] = exp2f(s[nt][1] - mn_g);
            s[nt][2] = exp2f(s[nt][2] - mn_g8);
            s[nt][3] = exp2f(s[nt][3] - mn_g8);
            sum_g  += s[nt][0] + s[nt][1];
            sum_g8 += s[nt][2] + s[nt][3];
        }
#pragma unroll
        for (int off = 1; off <= 2; off <<= 1) {
            sum_g  += __shfl_xor_sync(0xffffffffu, sum_g,  off);
            sum_g8 += __shfl_xor_sync(0xffffffffu, sum_g8, off);
        }
        l_g  = l_g  * alpha_g  + sum_g;
        l_g8 = l_g8 * alpha_g8 + sum_g8;
#pragma unroll
        for (int nt = 0; nt < 8; ++nt) {
            o[nt][0] *= alpha_g;  o[nt][1] *= alpha_g;
            o[nt][2] *= alpha_g8; o[nt][3] *= alpha_g8;
        }

        // ---- O += P V : P fp16, V fp16 hi/lo (2 mma per k16) ----
#pragma unroll
        for (int ks = 0; ks < 4; ++ks) {
            uint32_t pf[4];
            pf[0] = cvt2_f16(s[2 * ks][0],     s[2 * ks][1]);
            pf[1] = cvt2_f16(s[2 * ks][2],     s[2 * ks][3]);
            pf[2] = cvt2_f16(s[2 * ks + 1][0], s[2 * ks + 1][1]);
            pf[3] = cvt2_f16(s[2 * ks + 1][2], s[2 * ks + 1][3]);
#pragma unroll
            for (int pr = 0; pr < 4; ++pr) {
                uint32_t voff = vPairOff + (uint32_t)(ks * 16 * 72 + pr * 16) * 2 + kOff;
                uint32_t vh[4], vl[4];
                ldsm_x4_trans(vh, Vhi_b + voff);
                ldsm_x4_trans(vl, Vlo_b + voff);
                mma_f16(o[2 * pr],     pf, &vh[0]);
                mma_f16(o[2 * pr],     pf, &vl[0]);
                mma_f16(o[2 * pr + 1], pf, &vh[2]);
                mma_f16(o[2 * pr + 1], pf, &vl[2]);
            }
        }
    }

    float inv_g  = 1.f / l_g;
    float inv_g8 = 1.f / l_g8;
    const size_t row_g  = (size_t)(b * kTQ + q0 + m0w + g) * kC + h * 64;
    const size_t row_g8 = row_g + 8 * kC;
#pragma unroll
    for (int nt = 0; nt < 8; ++nt) {
        int col = nt * 8 + 2 * tg;
        {
            float x = o[nt][0] * inv_g, y = o[nt][1] * inv_g;
            __nv_bfloat16 h0, h1, l0, l1;
            split_bf16(x, h0, l0);
            split_bf16(y, h1, l1);
            *(uint32_t*)(Oh + row_g + col) = pack2(h0, h1);
            *(uint32_t*)(Ol + row_g + col) = pack2(l0, l1);
        }
        {
            float x = o[nt][2] * inv_g8, y = o[nt][3] * inv_g8;
            __nv_bfloat16 h0, h1, l0, l1;
            split_bf16(x, h0, l0);
            split_bf16(y, h1, l1);
            *(uint32_t*)(Oh + row_g8 + col) = pack2(h0, h1);
            *(uint32_t*)(Ol + row_g8 + col) = pack2(l0, l1);
        }
    }
}

// ---------------------------------------------------------------------------
extern "C" void kernel_launch(void* const* d_in, const int* in_sizes, int n_in,
                              void* d_out, int out_size) {
    const float* x_q  = (const float*)d_in[0];
    const float* x_kv = (const float*)d_in[1];
    const int* q_mask  = (const int*)d_in[2];
    const int* kv_mask = (const int*)d_in[3];
    const float* W_q  = (const float*)d_in[4];
    const float* W_kv = (const float*)d_in[5];
    const float* W_c  = (const float*)d_in[6];
    float* out = (float*)d_out;

    void* p;
    __nv_bfloat16 *xqh, *xql, *xkvh, *xkvl;
    __nv_bfloat16 *wqh, *wql, *wkvh, *wkvl, *wch, *wcl;
    __nv_bfloat16 *ah, *al;
    __half *qf, *kf, *vh, *vl;
    cudaGetSymbolAddress(&p, g_xqh);  xqh  = (__nv_bfloat16*)p;
    cudaGetSymbolAddress(&p, g_xql);  xql  = (__nv_bfloat16*)p;
    cudaGetSymbolAddress(&p, g_xkvh); xkvh = (__nv_bfloat16*)p;
    cudaGetSymbolAddress(&p, g_xkvl); xkvl = (__nv_bfloat16*)p;
    cudaGetSymbolAddress(&p, g_wqTh);  wqh  = (__nv_bfloat16*)p;
    cudaGetSymbolAddress(&p, g_wqTl);  wql  = (__nv_bfloat16*)p;
    cudaGetSymbolAddress(&p, g_wkvTh); wkvh = (__nv_bfloat16*)p;
    cudaGetSymbolAddress(&p, g_wkvTl); wkvl = (__nv_bfloat16*)p;
    cudaGetSymbolAddress(&p, g_wcTh);  wch  = (__nv_bfloat16*)p;
    cudaGetSymbolAddress(&p, g_wcTl);  wcl  = (__nv_bfloat16*)p;
    cudaGetSymbolAddress(&p, g_qf); qf = (__half*)p;
    cudaGetSymbolAddress(&p, g_kf); kf = (__half*)p;
    cudaGetSymbolAddress(&p, g_vh); vh = (__half*)p;
    cudaGetSymbolAddress(&p, g_vl); vl = (__half*)p;
    cudaGetSymbolAddress(&p, g_ah); ah = (__nv_bfloat16*)p;
    cudaGetSymbolAddress(&p, g_al); al = (__nv_bfloat16*)p;

    rope_tables_kernel<<<(kTKV * 32 + 255) / 256, 256>>>();

    int total4 = kM * kC / 4;
    split_x_kernel<<<(total4 + 255) / 256, 256>>>(x_q,  xqh,  xql,  total4);
    split_x_kernel<<<(total4 + 255) / 256, 256>>>(x_kv, xkvh, xkvl, total4);
    transpose_split_kernel<<<dim3(1024 / 32, 1024 / 32), dim3(32, 8)>>>(W_q,  wqh,  wql,  1024, 1024);
    transpose_split_kernel<<<dim3(2048 / 32, 1024 / 32), dim3(32, 8)>>>(W_kv, wkvh, wkvl, 1024, 2048);
    transpose_split_kernel<<<dim3(1024 / 32, 1024 / 32), dim3(32, 8)>>>(W_c,  wch,  wcl,  1024, 1024);

    // Q projection + rope + scale(log2e) -> fp16 single
    gemm_ps_kernel<1><<<dim3(kC / 128, kM / 128), 256>>>(
        xqh, xql, wqh, wql, nullptr, qf, nullptr, nullptr, kM, kC, kC);
    // KV projection: K rope -> fp16 single; V -> fp16 hi/lo
    gemm_ps_kernel<2><<<dim3(2 * kC / 128, kM / 128), 256>>>(
        xkvh, xkvl, wkvh, wkvl, nullptr, kf, vh, vl, kM, 2 * kC, kC);

    cudaFuncSetAttribute(flash_mma_kernel, cudaFuncAttributeMaxDynamicSharedMemorySize, kFlashSmem);
    flash_mma_kernel<<<dim3(kTQ / 128, kH, kB), 256, kFlashSmem>>>(
        qf, kf, vh, vl, q_mask, kv_mask, ah, al);

    // output projection (bf16x3) -> fp32 out
    gemm_ps_kernel<0><<<dim3(kC / 128, kM / 128), 256>>>(
        ah, al, wch, wcl, out, nullptr, nullptr, nullptr, kM, kC, kC);
}

// round 17
// speedup vs baseline: 1.9784x; 1.5220x over previous
#include <cuda_runtime.h>
#include <cuda_bf16.h>
#include <cuda_fp16.h>
#include <math.h>
#include <stdint.h>

constexpr int kB   = 4;
constexpr int kTQ  = 2048;
constexpr int kTKV = 2048;
constexpr int kC   = 1024;
constexpr int kD   = 64;
constexpr int kH   = 16;
constexpr int kM   = kB * kTQ;

__device__ float g_sin[kTKV * (kD / 2)];
__device__ float g_cos[kTKV * (kD / 2)];
// single fp16 operands everywhere
__device__ __half g_xqf[(size_t)kM * kC];
__device__ __half g_xkvf[(size_t)kM * kC];
__device__ __half g_wqTf[1024 * 1024];
__device__ __half g_wkvTf[2048 * 1024];
__device__ __half g_wcTf[1024 * 1024];
__device__ __half g_qf[(size_t)kM * kC];
__device__ __half g_kf[(size_t)kM * kC];
__device__ __half g_vh[(size_t)kM * kC], g_vl[(size_t)kM * kC];
__device__ __half g_af[(size_t)kM * kC];

// ---------------------------------------------------------------------------
__device__ __forceinline__ uint32_t smem_u32(const void* p) {
    return (uint32_t)__cvta_generic_to_shared(p);
}
__device__ __forceinline__ void ldsm_x4(uint32_t* r, uint32_t addr) {
    asm volatile("ldmatrix.sync.aligned.m8n8.x4.shared.b16 {%0,%1,%2,%3}, [%4];"
                 : "=r"(r[0]), "=r"(r[1]), "=r"(r[2]), "=r"(r[3]) : "r"(addr));
}
__device__ __forceinline__ void ldsm_x2(uint32_t* r, uint32_t addr) {
    asm volatile("ldmatrix.sync.aligned.m8n8.x2.shared.b16 {%0,%1}, [%2];"
                 : "=r"(r[0]), "=r"(r[1]) : "r"(addr));
}
__device__ __forceinline__ void ldsm_x4_trans(uint32_t* r, uint32_t addr) {
    asm volatile("ldmatrix.sync.aligned.m8n8.x4.trans.shared.b16 {%0,%1,%2,%3}, [%4];"
                 : "=r"(r[0]), "=r"(r[1]), "=r"(r[2]), "=r"(r[3]) : "r"(addr));
}
__device__ __forceinline__ void mma_f16(float* c, const uint32_t* a, const uint32_t* b) {
    asm volatile(
        "mma.sync.aligned.m16n8k16.row.col.f32.f16.f16.f32 "
        "{%0,%1,%2,%3}, {%4,%5,%6,%7}, {%8,%9}, {%0,%1,%2,%3};\n"
        : "+f"(c[0]), "+f"(c[1]), "+f"(c[2]), "+f"(c[3])
        : "r"(a[0]), "r"(a[1]), "r"(a[2]), "r"(a[3]), "r"(b[0]), "r"(b[1]));
}
__device__ __forceinline__ uint32_t pack2h(__half a, __half b) {
    __half2 t; t.x = a; t.y = b;
    return *reinterpret_cast<uint32_t*>(&t);
}
__device__ __forceinline__ uint32_t cvt2_f16(float lo, float hi) {
    uint32_t r;
    asm("cvt.rn.f16x2.f32 %0, %1, %2;" : "=r"(r) : "f"(hi), "f"(lo));
    return r;
}

// ---------------------------------------------------------------------------
__global__ void rope_tables_kernel() {
    int idx = blockIdx.x * blockDim.x + threadIdx.x;
    if (idx >= kTKV * (kD / 2)) return;
    int t = idx >> 5;
    int i = idx & 31;
    double freq = pow(10000.0, -((2.0 * i + 1.0) / (double)kD));
    double ang = (double)(t + 1) * freq;
    g_sin[idx] = (float)sin(ang);
    g_cos[idx] = (float)cos(ang);
}

__global__ void cvt_x_kernel(const float* __restrict__ X,
                             __half* __restrict__ F, int total4) {
    int idx = blockIdx.x * blockDim.x + threadIdx.x;
    if (idx >= total4) return;
    float4 v = ((const float4*)X)[idx];
    ((uint2*)F)[idx] = make_uint2(cvt2_f16(v.x, v.y), cvt2_f16(v.z, v.w));
}

__global__ void transpose_cvt_kernel(const float* __restrict__ W,
                                     __half* __restrict__ T, int K, int N) {
    __shared__ float t[32][33];
    int n0 = blockIdx.x * 32, k0 = blockIdx.y * 32;
    for (int r = threadIdx.y; r < 32; r += 8)
        t[r][threadIdx.x] = W[(size_t)(k0 + r) * N + n0 + threadIdx.x];
    __syncthreads();
    for (int r = threadIdx.y; r < 32; r += 8)
        T[(size_t)(n0 + r) * K + k0 + threadIdx.x] = __float2half(t[threadIdx.x][r]);
}

// ---------------------------------------------------------------------------
// Single-fp16 GEMM: C = A @ B^T layout, 1 mma per k16.
// MODE 0: fp32 C. MODE 1: rope+scale -> fp16 Q. MODE 2: K rope fp16 / V fp16 hi+lo.
// ---------------------------------------------------------------------------
constexpr int kLD = 40;

template <int MODE>
__global__ __launch_bounds__(256)
void gemm_f16_kernel(const __half* __restrict__ A,
                     const __half* __restrict__ B,
                     float* __restrict__ Cf,
                     __half* __restrict__ O1f,
                     __half* __restrict__ O2h, __half* __restrict__ O2l,
                     int M, int N, int K) {
    __shared__ __align__(16) __half sA[128 * kLD];
    __shared__ __align__(16) __half sB[128 * kLD];

    const int tid  = threadIdx.x;
    const int warp = tid >> 5, lane = tid & 31;
    const int wm = warp >> 2, wn = warp & 3;
    const int m0 = blockIdx.y * 128, n0 = blockIdx.x * 128;

    const int row = tid >> 1;
    const int ko  = (tid & 1) * 16;
    const __half* aP = A + (size_t)(m0 + row) * K + ko;
    const __half* bP = B + (size_t)(n0 + row) * K + ko;

    uint4 pA[2], pB[2];
#pragma unroll
    for (int u = 0; u < 2; ++u) {
        pA[u] = *(const uint4*)(aP + u * 8);
        pB[u] = *(const uint4*)(bP + u * 8);
    }

    float acc[4][4][4];
#pragma unroll
    for (int mt = 0; mt < 4; ++mt)
#pragma unroll
        for (int nt = 0; nt < 4; ++nt)
#pragma unroll
            for (int e = 0; e < 4; ++e) acc[mt][nt][e] = 0.f;

    const uint32_t sA_b = smem_u32(sA), sB_b = smem_u32(sB);
    const int g8 = lane & 7, tq = lane >> 3;

    const int nk = K / 32;
    for (int kt = 0; kt < nk; ++kt) {
#pragma unroll
        for (int u = 0; u < 2; ++u) {
            *(uint4*)&sA[row * kLD + ko + u * 8] = pA[u];
            *(uint4*)&sB[row * kLD + ko + u * 8] = pB[u];
        }
        __syncthreads();

        if (kt + 1 < nk) {
            int kc = (kt + 1) * 32;
#pragma unroll
            for (int u = 0; u < 2; ++u) {
                pA[u] = *(const uint4*)(aP + kc + u * 8);
                pB[u] = *(const uint4*)(bP + kc + u * 8);
            }
        }

#pragma unroll
        for (int s = 0; s < 2; ++s) {
            uint32_t bf[4][2];
#pragma unroll
            for (int nt = 0; nt < 4; ++nt) {
                uint32_t off = (uint32_t)(((wn * 32 + nt * 8 + g8) * kLD + s * 16 + ((tq & 1) << 3)) * 2);
                ldsm_x2(bf[nt], sB_b + off);
            }
#pragma unroll
            for (int mt = 0; mt < 4; ++mt) {
                uint32_t offA = (uint32_t)(((wm * 64 + mt * 16 + ((tq & 1) << 3) + g8) * kLD
                                            + s * 16 + ((tq >> 1) << 3)) * 2);
                uint32_t af[4];
                ldsm_x4(af, sA_b + offA);
#pragma unroll
                for (int nt = 0; nt < 4; ++nt)
                    mma_f16(acc[mt][nt], af, bf[nt]);
            }
        }
        __syncthreads();
    }

    const int gq = lane >> 2, tg2 = 2 * (lane & 3);
#pragma unroll
    for (int mt = 0; mt < 4; ++mt) {
#pragma unroll
        for (int nt = 0; nt < 4; ++nt) {
            int col = n0 + wn * 32 + nt * 8 + tg2;
#pragma unroll
            for (int half = 0; half < 2; ++half) {
                int r = m0 + wm * 64 + mt * 16 + gq + half * 8;
                float x = acc[mt][nt][half * 2 + 0];
                float y = acc[mt][nt][half * 2 + 1];
                if (MODE == 0) {
                    *(float2*)(Cf + (size_t)r * N + col) = make_float2(x, y);
                } else if (MODE == 1) {
                    int t = r & (kTQ - 1);
                    int i = (col & 63) >> 1;
                    float si = g_sin[t * 32 + i], co = g_cos[t * 32 + i];
                    const float sc = 0.18033688011112042f;  // 0.125 * log2(e)
                    float xq = (x * co - y * si) * sc;
                    float yq = (x * si + y * co) * sc;
                    size_t o = (size_t)r * kC + col;
                    *(uint32_t*)(O1f + o) = cvt2_f16(xq, yq);
                } else {
                    if (col < kC) {
                        int t = r & (kTKV - 1);
                        int i = (col & 63) >> 1;
                        float si = g_sin[t * 32 + i], co = g_cos[t * 32 + i];
                        float xk = x * co - y * si;
                        float yk = x * si + y * co;
                        size_t o = (size_t)r * kC + col;
                        *(uint32_t*)(O1f + o) = cvt2_f16(xk, yk);
                    } else {
                        __half h0 = __float2half(x);
                        __half l0 = __float2half(x - __half2float(h0));
                        __half h1 = __float2half(y);
                        __half l1 = __float2half(y - __half2float(h1));
                        size_t o = (size_t)r * kC + (col - kC);
                        *(uint32_t*)(O2h + o) = pack2h(h0, h1);
                        *(uint32_t*)(O2l + o) = pack2h(l0, l1);
                    }
                }
            }
        }
    }
}

// ---------------------------------------------------------------------------
// Flash attention (R16-proven core). Epilogue writes single fp16 A.
// ---------------------------------------------------------------------------
constexpr int kFQ = 128 * 72;
constexpr int kFT = 64 * 72;
constexpr int kFlashSmem = (kFQ + 6 * kFT) * 2 + 2 * 64 * 4;

__global__ __launch_bounds__(256, 2)
void flash_mma_kernel(const __half* __restrict__ Qf,
                      const __half* __restrict__ Kf,
                      const __half* __restrict__ Vh, const __half* __restrict__ Vl,
                      const int* __restrict__ qmask, const int* __restrict__ kvmask,
                      __half* __restrict__ Of) {
    extern __shared__ char smc[];
    __half* Qs = (__half*)smc;
    __half* Ks = Qs + kFQ;
    __half* Vhi = Ks + 2 * kFT;
    __half* Vlo = Vhi + 2 * kFT;
    float* km = (float*)(Vlo + 2 * kFT);

    const int tid = threadIdx.x;
    const int warp = tid >> 5, lane = tid & 31;
    const int g = lane >> 2, tg = lane & 3;
    const int m0w = warp * 16;
    const int q0 = blockIdx.x * 128;
    const int h  = blockIdx.y;
    const int b  = blockIdx.z;

    {
        int row = tid >> 1, cb = (tid & 1) * 32;
        size_t src = (size_t)(b * kTQ + q0 + row) * kC + h * 64 + cb;
        int dst = row * 72 + cb;
#pragma unroll
        for (int u = 0; u < 4; ++u)
            *(uint4*)&Qs[dst + u * 8] = *(const uint4*)(Qf + src + u * 8);
    }
    {
        int j = tid >> 2, cb = (tid & 3) * 16;
        size_t src = (size_t)(b * kTKV + j) * kC + h * 64 + cb;
        int dst = j * 72 + cb;
#pragma unroll
        for (int u = 0; u < 2; ++u) {
            *(uint4*)&Ks[dst + u * 8]  = *(const uint4*)(Kf + src + u * 8);
            *(uint4*)&Vhi[dst + u * 8] = *(const uint4*)(Vh + src + u * 8);
            *(uint4*)&Vlo[dst + u * 8] = *(const uint4*)(Vl + src + u * 8);
        }
        if (tid < 64) km[tid] = (kvmask[b * kTKV + tid] != 0) ? 1.f : 0.f;
    }

    const float qok_g  = (qmask[b * kTQ + q0 + m0w + g]     != 0) ? 1.f : 0.f;
    const float qok_g8 = (qmask[b * kTQ + q0 + m0w + g + 8] != 0) ? 1.f : 0.f;

    float o[8][4];
#pragma unroll
    for (int nt = 0; nt < 8; ++nt)
#pragma unroll
        for (int e = 0; e < 4; ++e) o[nt][e] = 0.f;
    float m_g = -INFINITY, m_g8 = -INFINITY, l_g = 0.f, l_g8 = 0.f;

    const uint32_t Qs_b = smem_u32(Qs);
    const uint32_t Ks_b = smem_u32(Ks);
    const uint32_t Vhi_b = smem_u32(Vhi), Vlo_b = smem_u32(Vlo);

    const uint32_t kPairOff = (uint32_t)((((lane >> 4) << 3) + (lane & 7)) * 72
                                         + (((lane >> 3) & 1) << 3)) * 2;
    const uint32_t vPairOff = (uint32_t)(((((lane >> 3) & 1) << 3) + (lane & 7)) * 72
                                         + ((lane >> 4) << 3)) * 2;

    const int nTiles = kTKV / 64;
    for (int kt = 0; kt < nTiles; ++kt) {
        __syncthreads();
        const int buf = kt & 1;
        const uint32_t kOff = (uint32_t)buf * (kFT * 2);

        if (kt + 1 < nTiles) {
            int k0n = (kt + 1) * 64;
            int nb = buf ^ 1;
            int j = tid >> 2, cb = (tid & 3) * 16;
            size_t src = (size_t)(b * kTKV + k0n + j) * kC + h * 64 + cb;
            int dst = nb * kFT + j * 72 + cb;
#pragma unroll
            for (int u = 0; u < 2; ++u) {
                *(uint4*)&Ks[dst + u * 8]  = *(const uint4*)(Kf + src + u * 8);
                *(uint4*)&Vhi[dst + u * 8] = *(const uint4*)(Vh + src + u * 8);
                *(uint4*)&Vlo[dst + u * 8] = *(const uint4*)(Vl + src + u * 8);
            }
            if (tid < 64) km[nb * 64 + tid] = (kvmask[b * kTKV + k0n + tid] != 0) ? 1.f : 0.f;
        }

        float s[8][4];
#pragma unroll
        for (int nt = 0; nt < 8; ++nt)
#pragma unroll
            for (int e = 0; e < 4; ++e) s[nt][e] = 0.f;

#pragma unroll
        for (int ks = 0; ks < 4; ++ks) {
            uint32_t aoff = (uint32_t)(((m0w + (lane & 15)) * 72 + ks * 16 + ((lane >> 4) << 3)) * 2);
            uint32_t aq[4];
            ldsm_x4(aq, Qs_b + aoff);
#pragma unroll
            for (int pr = 0; pr < 4; ++pr) {
                uint32_t boff = kPairOff + (uint32_t)(pr * 16 * 72 + ks * 16) * 2 + kOff;
                uint32_t bk[4];
                ldsm_x4(bk, Ks_b + boff);
                mma_f16(s[2 * pr],     aq, &bk[0]);
                mma_f16(s[2 * pr + 1], aq, &bk[2]);
            }
        }

        float mx_g = -INFINITY, mx_g8 = -INFINITY;
#pragma unroll
        for (int nt = 0; nt < 8; ++nt) {
            float k0v = km[buf * 64 + nt * 8 + 2 * tg];
            float k1v = km[buf * 64 + nt * 8 + 2 * tg + 1];
            s[nt][0] = (qok_g  * k0v != 0.f) ? s[nt][0] : -1e9f;
            s[nt][1] = (qok_g  * k1v != 0.f) ? s[nt][1] : -1e9f;
            s[nt][2] = (qok_g8 * k0v != 0.f) ? s[nt][2] : -1e9f;
            s[nt][3] = (qok_g8 * k1v != 0.f) ? s[nt][3] : -1e9f;
            mx_g  = fmaxf(mx_g,  fmaxf(s[nt][0], s[nt][1]));
            mx_g8 = fmaxf(mx_g8, fmaxf(s[nt][2], s[nt][3]));
        }
#pragma unroll
        for (int off = 1; off <= 2; off <<= 1) {
            mx_g  = fmaxf(mx_g,  __shfl_xor_sync(0xffffffffu, mx_g,  off));
            mx_g8 = fmaxf(mx_g8, __shfl_xor_sync(0xffffffffu, mx_g8, off));
        }
        float mn_g  = fmaxf(m_g,  mx_g);
        float mn_g8 = fmaxf(m_g8, mx_g8);
        float alpha_g  = exp2f(m_g  - mn_g);
        float alpha_g8 = exp2f(m_g8 - mn_g8);
        m_g = mn_g; m_g8 = mn_g8;

        float sum_g = 0.f, sum_g8 = 0.f;
#pragma unroll
        for (int nt = 0; nt < 8; ++nt) {
            s[nt][0] = exp2f(s[nt][0] - mn_g);
            s[nt][1] = exp2f(s[nt][1] - mn_g);
            s[nt][2] = exp2f(s[nt][2] - mn_g8);
            s[nt][3] = exp2f(s[nt][3] - mn_g8);
            sum_g  += s[nt][0] + s[nt][1];
            sum_g8 += s[nt][2] + s[nt][3];
        }
#pragma unroll
        for (int off = 1; off <= 2; off <<= 1) {
            sum_g  += __shfl_xor_sync(0xffffffffu, sum_g,  off);
            sum_g8 += __shfl_xor_sync(0xffffffffu, sum_g8, off);
        }
        l_g  = l_g  * alpha_g  + sum_g;
        l_g8 = l_g8 * alpha_g8 + sum_g8;
#pragma unroll
        for (int nt = 0; nt < 8; ++nt) {
            o[nt][0] *= alpha_g;  o[nt][1] *= alpha_g;
            o[nt][2] *= alpha_g8; o[nt][3] *= alpha_g8;
        }

#pragma unroll
        for (int ks = 0; ks < 4; ++ks) {
            uint32_t pf[4];
            pf[0] = cvt2_f16(s[2 * ks][0],     s[2 * ks][1]);
            pf[1] = cvt2_f16(s[2 * ks][2],     s[2 * ks][3]);
            pf[2] = cvt2_f16(s[2 * ks + 1][0], s[2 * ks + 1][1]);
            pf[3] = cvt2_f16(s[2 * ks + 1][2], s[2 * ks + 1][3]);
#pragma unroll
            for (int pr = 0; pr < 4; ++pr) {
                uint32_t voff = vPairOff + (uint32_t)(ks * 16 * 72 + pr * 16) * 2 + kOff;
                uint32_t vh[4], vl[4];
                ldsm_x4_trans(vh, Vhi_b + voff);
                ldsm_x4_trans(vl, Vlo_b + voff);
                mma_f16(o[2 * pr],     pf, &vh[0]);
                mma_f16(o[2 * pr],     pf, &vl[0]);
                mma_f16(o[2 * pr + 1], pf, &vh[2]);
                mma_f16(o[2 * pr + 1], pf, &vl[2]);
            }
        }
    }

    float inv_g  = 1.f / l_g;
    float inv_g8 = 1.f / l_g8;
    const size_t row_g  = (size_t)(b * kTQ + q0 + m0w + g) * kC + h * 64;
    const size_t row_g8 = row_g + 8 * kC;
#pragma unroll
    for (int nt = 0; nt < 8; ++nt) {
        int col = nt * 8 + 2 * tg;
        *(uint32_t*)(Of + row_g  + col) = cvt2_f16(o[nt][0] * inv_g,  o[nt][1] * inv_g);
        *(uint32_t*)(Of + row_g8 + col) = cvt2_f16(o[nt][2] * inv_g8, o[nt][3] * inv_g8);
    }
}

// ---------------------------------------------------------------------------
extern "C" void kernel_launch(void* const* d_in, const int* in_sizes, int n_in,
                              void* d_out, int out_size) {
    const float* x_q  = (const float*)d_in[0];
    const float* x_kv = (const float*)d_in[1];
    const int* q_mask  = (const int*)d_in[2];
    const int* kv_mask = (const int*)d_in[3];
    const float* W_q  = (const float*)d_in[4];
    const float* W_kv = (const float*)d_in[5];
    const float* W_c  = (const float*)d_in[6];
    float* out = (float*)d_out;

    void* p;
    __half *xqf, *xkvf, *wqf, *wkvf, *wcf;
    __half *qf, *kf, *vh, *vl, *af;
    cudaGetSymbolAddress(&p, g_xqf);   xqf  = (__half*)p;
    cudaGetSymbolAddress(&p, g_xkvf);  xkvf = (__half*)p;
    cudaGetSymbolAddress(&p, g_wqTf);  wqf  = (__half*)p;
    cudaGetSymbolAddress(&p, g_wkvTf); wkvf = (__half*)p;
    cudaGetSymbolAddress(&p, g_wcTf);  wcf  = (__half*)p;
    cudaGetSymbolAddress(&p, g_qf); qf = (__half*)p;
    cudaGetSymbolAddress(&p, g_kf); kf = (__half*)p;
    cudaGetSymbolAddress(&p, g_vh); vh = (__half*)p;
    cudaGetSymbolAddress(&p, g_vl); vl = (__half*)p;
    cudaGetSymbolAddress(&p, g_af); af = (__half*)p;

    rope_tables_kernel<<<(kTKV * 32 + 255) / 256, 256>>>();

    int total4 = kM * kC / 4;
    cvt_x_kernel<<<(total4 + 255) / 256, 256>>>(x_q,  xqf,  total4);
    cvt_x_kernel<<<(total4 + 255) / 256, 256>>>(x_kv, xkvf, total4);
    transpose_cvt_kernel<<<dim3(1024 / 32, 1024 / 32), dim3(32, 8)>>>(W_q,  wqf,  1024, 1024);
    transpose_cvt_kernel<<<dim3(2048 / 32, 1024 / 32), dim3(32, 8)>>>(W_kv, wkvf, 1024, 2048);
    transpose_cvt_kernel<<<dim3(1024 / 32, 1024 / 32), dim3(32, 8)>>>(W_c,  wcf,  1024, 1024);

    // Q projection + rope + scale(log2e) -> fp16
    gemm_f16_kernel<1><<<dim3(kC / 128, kM / 128), 256>>>(
        xqf, wqf, nullptr, qf, nullptr, nullptr, kM, kC, kC);
    // KV projection: K rope -> fp16; V -> fp16 hi/lo
    gemm_f16_kernel<2><<<dim3(2 * kC / 128, kM / 128), 256>>>(
        xkvf, wkvf, nullptr, kf, vh, vl, kM, 2 * kC, kC);

    cudaFuncSetAttribute(flash_mma_kernel, cudaFuncAttributeMaxDynamicSharedMemorySize, kFlashSmem);
    flash_mma_kernel<<<dim3(kTQ / 128, kH, kB), 256, kFlashSmem>>>(
        qf, kf, vh, vl, q_mask, kv_mask, af);

    // output projection (fp16) -> fp32 out
    gemm_f16_kernel<0><<<dim3(kC / 128, kM / 128), 256>>>(
        af, wcf, out, nullptr, nullptr, nullptr, kM, kC, kC);
}